// round 8
// baseline (speedup 1.0000x reference)
#include <cuda_runtime.h>
#include <cuda_bf16.h>
#include <cstdint>

#define M_NODES 10000
#define K_IN    512
#define N_HID   512
#define N_EDGES 160000

// Scratch (no allocations allowed)
__device__ float         g_xfts[M_NODES * N_HID];
__device__ __nv_bfloat16 g_xhi[M_NODES * K_IN];
__device__ __nv_bfloat16 g_xlo[M_NODES * K_IN];
__device__ __nv_bfloat16 g_whi[N_HID * K_IN];
__device__ __nv_bfloat16 g_wlo[N_HID * K_IN];
__device__ int           g_rowptr[M_NODES + 1];

// ---------------------------------------------------------------------------
// Fused prep: split X / W (fp32 -> bf16 hi+lo) with 8 batched loads/thread,
// plus rowptr blocks.
//   X: 1,280,000 float4s -> 625 blocks * 2048
//   W:    65,536 float4s ->  32 blocks * 2048
// ---------------------------------------------------------------------------
#define XBLK 625
#define WBLK 32
#define RBLK 40

__device__ __forceinline__ void split4(float4 v, __nv_bfloat16* hi_arr,
                                       __nv_bfloat16* lo_arr, int i)
{
    __nv_bfloat16 hx = __float2bfloat16_rn(v.x);
    __nv_bfloat16 hy = __float2bfloat16_rn(v.y);
    __nv_bfloat16 hz = __float2bfloat16_rn(v.z);
    __nv_bfloat16 hw = __float2bfloat16_rn(v.w);
    __nv_bfloat16 lx = __float2bfloat16_rn(v.x - __bfloat162float(hx));
    __nv_bfloat16 ly = __float2bfloat16_rn(v.y - __bfloat162float(hy));
    __nv_bfloat16 lz = __float2bfloat16_rn(v.z - __bfloat162float(hz));
    __nv_bfloat16 lw = __float2bfloat16_rn(v.w - __bfloat162float(hw));
    reinterpret_cast<__nv_bfloat162*>(hi_arr)[2 * i]     = __nv_bfloat162(hx, hy);
    reinterpret_cast<__nv_bfloat162*>(hi_arr)[2 * i + 1] = __nv_bfloat162(hz, hw);
    reinterpret_cast<__nv_bfloat162*>(lo_arr)[2 * i]     = __nv_bfloat162(lx, ly);
    reinterpret_cast<__nv_bfloat162*>(lo_arr)[2 * i + 1] = __nv_bfloat162(lz, lw);
}

__global__ __launch_bounds__(256) void prep_kernel(
    const float* __restrict__ x,
    const float* __restrict__ fc_w,
    const int* __restrict__ adj_row)
{
    const int b = blockIdx.x;
    const int t = threadIdx.x;
    if (b < XBLK) {
        const int i0 = b * 2048 + t;
        float4 v[8];
#pragma unroll
        for (int k = 0; k < 8; k++)
            v[k] = reinterpret_cast<const float4*>(x)[i0 + k * 256];
#pragma unroll
        for (int k = 0; k < 8; k++)
            split4(v[k], g_xhi, g_xlo, i0 + k * 256);
    } else if (b < XBLK + WBLK) {
        const int i0 = (b - XBLK) * 2048 + t;
        float4 v[8];
#pragma unroll
        for (int k = 0; k < 8; k++)
            v[k] = reinterpret_cast<const float4*>(fc_w)[i0 + k * 256];
#pragma unroll
        for (int k = 0; k < 8; k++)
            split4(v[k], g_whi, g_wlo, i0 + k * 256);
    } else {
        int r = (b - XBLK - WBLK) * 256 + t;
        if (r > M_NODES) return;
        int lo = 0, hi = N_EDGES;
        while (lo < hi) {
            int mid = (lo + hi) >> 1;
            if (adj_row[mid] < r) lo = mid + 1; else hi = mid;
        }
        g_rowptr[r] = lo;
    }
}

// ---------------------------------------------------------------------------
// Tensor-core GEMM (mma.sync bf16, 3-term split), ldmatrix fragment loads.
// CTA 128x64, BK=32, 256 threads = 8 warps (4m x 2n), warp tile 32x32.
// cp.async double buffer; 30KB/stage -> 2 CTAs/SM; ONE barrier per K-tile.
// ---------------------------------------------------------------------------
#define BM 128
#define BN 64
#define BK 32
#define KSTRIDE 40                        // bf16 per smem row (32 + 8 pad)
#define A_LO_OFF 5120                     // 128*40
#define B_OFF    10240
#define B_LO_REL 2560                     // 64*40
#define STAGE    15360                    // elements per stage
#define SMEM_BYTES (2 * STAGE * 2)        // 61440

__device__ __forceinline__ void cp_async16(uint32_t dst, const void* src, bool pred)
{
    int sz = pred ? 16 : 0;
    asm volatile("cp.async.cg.shared.global [%0], [%1], 16, %2;\n"
                 :: "r"(dst), "l"(src), "r"(sz));
}
__device__ __forceinline__ void cp_commit() { asm volatile("cp.async.commit_group;\n"); }
__device__ __forceinline__ void cp_wait0()  { asm volatile("cp.async.wait_group 0;\n"); }

#define LDSM_X4(r0, r1, r2, r3, addr) \
    asm volatile("ldmatrix.sync.aligned.m8n8.x4.shared.b16 {%0,%1,%2,%3}, [%4];" \
                 : "=r"(r0), "=r"(r1), "=r"(r2), "=r"(r3) : "r"(addr))

__device__ __forceinline__ void mma_bf16(float c[4], const uint32_t a[4],
                                         const uint32_t b[2])
{
    asm volatile(
        "mma.sync.aligned.m16n8k16.row.col.f32.bf16.bf16.f32 "
        "{%0,%1,%2,%3}, {%4,%5,%6,%7}, {%8,%9}, {%0,%1,%2,%3};\n"
        : "+f"(c[0]), "+f"(c[1]), "+f"(c[2]), "+f"(c[3])
        : "r"(a[0]), "r"(a[1]), "r"(a[2]), "r"(a[3]), "r"(b[0]), "r"(b[1]));
}

__global__ __launch_bounds__(256, 2) void gemm_tc_kernel()
{
    extern __shared__ __nv_bfloat16 smem[];
    const int tid  = threadIdx.x;
    const int lane = tid & 31;
    const int wid  = tid >> 5;            // 0..7
    const int wm   = (wid & 3) * 32;      // 4 warps over M
    const int wn   = (wid >> 2) * 32;     // 2 warps over N
    const int m0   = blockIdx.y * BM;
    const int n0   = blockIdx.x * BN;
    const int grp  = lane >> 2;           // 0..7
    const int tig  = lane & 3;            // 0..3

    const uint32_t smem_u32 = (uint32_t)__cvta_generic_to_shared(smem);

    float acc[2][4][4];
#pragma unroll
    for (int mi = 0; mi < 2; mi++)
#pragma unroll
        for (int ni = 0; ni < 4; ni++)
#pragma unroll
            for (int q = 0; q < 4; q++) acc[mi][ni][q] = 0.f;

    // --- loaders ---
    const int rowA  = tid >> 1;           // 0..127
    const int halfA = tid & 1;
    const int gmA   = m0 + rowA;
    const bool pA   = (gmA < M_NODES);
    const int rowB  = tid >> 2;           // 0..63
    const int chB   = tid & 3;            // 0..3
    const int gnB   = n0 + rowB;          // < 512 always

    auto load_tile = [&](int buf, int k0) {
        uint32_t sbase = smem_u32 + (uint32_t)(buf * STAGE) * 2;
#pragma unroll
        for (int c = 0; c < 2; c++) {
            int ch = halfA * 2 + c;       // 0..3
            uint32_t dA = sbase + (uint32_t)(rowA * KSTRIDE + ch * 8) * 2;
            cp_async16(dA,                &g_xhi[(size_t)gmA * K_IN + k0 + ch * 8], pA);
            cp_async16(dA + A_LO_OFF * 2, &g_xlo[(size_t)gmA * K_IN + k0 + ch * 8], pA);
        }
        uint32_t dB = sbase + (uint32_t)(B_OFF + rowB * KSTRIDE + chB * 8) * 2;
        cp_async16(dB,                &g_whi[(size_t)gnB * K_IN + k0 + chB * 8], true);
        cp_async16(dB + B_LO_REL * 2, &g_wlo[(size_t)gnB * K_IN + k0 + chB * 8], true);
        cp_commit();
    };

    load_tile(0, 0);

    // ldmatrix per-lane address components
    const int a_row = wm + ((lane >> 3) & 1) * 8 + (lane & 7);
    const int a_seg = (lane >> 4) * 8;
    const int b_row = wn + (lane >> 4) * 8 + (lane & 7);
    const int b_seg = ((lane >> 3) & 1) * 8;

    const int NT = K_IN / BK;             // 16
    for (int t = 0; t < NT; t++) {
        cp_wait0();
        __syncthreads();                  // single barrier per K-tile
        if (t + 1 < NT) load_tile((t + 1) & 1, (t + 1) * BK);

        const uint32_t sbase = smem_u32 + (uint32_t)((t & 1) * STAGE) * 2;

#pragma unroll
        for (int ks = 0; ks < 2; ks++) {
            const int kcol = ks * 16;
            uint32_t ahi[2][4], alo[2][4];
#pragma unroll
            for (int mi = 0; mi < 2; mi++) {
                uint32_t addr = sbase + (uint32_t)((a_row + mi * 16) * KSTRIDE + a_seg + kcol) * 2;
                LDSM_X4(ahi[mi][0], ahi[mi][1], ahi[mi][2], ahi[mi][3], addr);
                LDSM_X4(alo[mi][0], alo[mi][1], alo[mi][2], alo[mi][3], addr + A_LO_OFF * 2);
            }
            uint32_t bhi[4][2], blo[4][2];
#pragma unroll
            for (int njp = 0; njp < 2; njp++) {
                uint32_t addr = sbase + (uint32_t)(B_OFF + (b_row + njp * 16) * KSTRIDE + b_seg + kcol) * 2;
                LDSM_X4(bhi[njp * 2][0], bhi[njp * 2][1],
                        bhi[njp * 2 + 1][0], bhi[njp * 2 + 1][1], addr);
                LDSM_X4(blo[njp * 2][0], blo[njp * 2][1],
                        blo[njp * 2 + 1][0], blo[njp * 2 + 1][1], addr + B_LO_REL * 2);
            }
            // term-major: 8 independent MMAs per term
#pragma unroll
            for (int mi = 0; mi < 2; mi++)
#pragma unroll
                for (int nj = 0; nj < 4; nj++)
                    mma_bf16(acc[mi][nj], ahi[mi], bhi[nj]);
#pragma unroll
            for (int mi = 0; mi < 2; mi++)
#pragma unroll
                for (int nj = 0; nj < 4; nj++)
                    mma_bf16(acc[mi][nj], ahi[mi], blo[nj]);
#pragma unroll
            for (int mi = 0; mi < 2; mi++)
#pragma unroll
                for (int nj = 0; nj < 4; nj++)
                    mma_bf16(acc[mi][nj], alo[mi], bhi[nj]);
        }
    }

    // --- epilogue (no smem use; no extra sync needed) ---
#pragma unroll
    for (int mi = 0; mi < 2; mi++) {
        int gm = m0 + wm + mi * 16 + grp;
#pragma unroll
        for (int nj = 0; nj < 4; nj++) {
            int gn = n0 + wn + nj * 8 + tig * 2;
            if (gm < M_NODES)
                *(float2*)&g_xfts[(size_t)gm * N_HID + gn] =
                    make_float2(acc[mi][nj][0], acc[mi][nj][1]);
            if (gm + 8 < M_NODES)
                *(float2*)&g_xfts[(size_t)(gm + 8) * N_HID + gn] =
                    make_float2(acc[mi][nj][2], acc[mi][nj][3]);
        }
    }
}

// ---------------------------------------------------------------------------
// SPMM + bias + PReLU (rowptr precomputed, 8-deep MLP)
// ---------------------------------------------------------------------------
__global__ __launch_bounds__(128) void spmm_bias_prelu_kernel(
    const float* __restrict__ adj_vals,
    const int* __restrict__ adj_col,
    const float* __restrict__ bias,
    const float* __restrict__ prelu_a,
    float* __restrict__ out)
{
    const int r = blockIdx.x;
    const int c = threadIdx.x * 4;
    const int start = g_rowptr[r];
    const int end   = g_rowptr[r + 1];

    float4 acc[8];
#pragma unroll
    for (int q = 0; q < 8; q++) acc[q] = make_float4(0.f, 0.f, 0.f, 0.f);

    int e = start;
    for (; e + 7 < end; e += 8) {
        float v[8]; int ci[8];
#pragma unroll
        for (int q = 0; q < 8; q++) {
            v[q]  = __ldg(&adj_vals[e + q]);
            ci[q] = __ldg(&adj_col[e + q]);
        }
        float4 f[8];
#pragma unroll
        for (int q = 0; q < 8; q++)
            f[q] = *reinterpret_cast<const float4*>(&g_xfts[(size_t)ci[q] * N_HID + c]);
#pragma unroll
        for (int q = 0; q < 8; q++) {
            acc[q].x += v[q] * f[q].x;
            acc[q].y += v[q] * f[q].y;
            acc[q].z += v[q] * f[q].z;
            acc[q].w += v[q] * f[q].w;
        }
    }
    for (; e + 3 < end; e += 4) {
        float v[4]; int ci[4];
#pragma unroll
        for (int q = 0; q < 4; q++) {
            v[q]  = __ldg(&adj_vals[e + q]);
            ci[q] = __ldg(&adj_col[e + q]);
        }
        float4 f[4];
#pragma unroll
        for (int q = 0; q < 4; q++)
            f[q] = *reinterpret_cast<const float4*>(&g_xfts[(size_t)ci[q] * N_HID + c]);
#pragma unroll
        for (int q = 0; q < 4; q++) {
            acc[q].x += v[q] * f[q].x;
            acc[q].y += v[q] * f[q].y;
            acc[q].z += v[q] * f[q].z;
            acc[q].w += v[q] * f[q].w;
        }
    }
    for (; e < end; e++) {
        const float v0 = __ldg(&adj_vals[e]);
        const int   c0 = __ldg(&adj_col[e]);
        const float4 f0 = *reinterpret_cast<const float4*>(&g_xfts[(size_t)c0 * N_HID + c]);
        acc[0].x += v0 * f0.x; acc[0].y += v0 * f0.y;
        acc[0].z += v0 * f0.z; acc[0].w += v0 * f0.w;
    }

    const float4 b4 = *reinterpret_cast<const float4*>(&bias[c]);
    const float a = *prelu_a;
    float4 o;
    o.x = ((acc[0].x + acc[1].x) + (acc[2].x + acc[3].x)) +
          ((acc[4].x + acc[5].x) + (acc[6].x + acc[7].x)) + b4.x;
    o.y = ((acc[0].y + acc[1].y) + (acc[2].y + acc[3].y)) +
          ((acc[4].y + acc[5].y) + (acc[6].y + acc[7].y)) + b4.y;
    o.z = ((acc[0].z + acc[1].z) + (acc[2].z + acc[3].z)) +
          ((acc[4].z + acc[5].z) + (acc[6].z + acc[7].z)) + b4.z;
    o.w = ((acc[0].w + acc[1].w) + (acc[2].w + acc[3].w)) +
          ((acc[4].w + acc[5].w) + (acc[6].w + acc[7].w)) + b4.w;
    o.x = (o.x >= 0.f) ? o.x : a * o.x;
    o.y = (o.y >= 0.f) ? o.y : a * o.y;
    o.z = (o.z >= 0.f) ? o.z : a * o.z;
    o.w = (o.w >= 0.f) ? o.w : a * o.w;
    *reinterpret_cast<float4*>(&out[(size_t)r * N_HID + c]) = o;
}

extern "C" void kernel_launch(void* const* d_in, const int* in_sizes, int n_in,
                              void* d_out, int out_size)
{
    const float* x        = (const float*)d_in[0];
    const float* fc_w     = (const float*)d_in[1];
    const float* bias     = (const float*)d_in[2];
    const float* prelu_a  = (const float*)d_in[3];
    const float* adj_vals = (const float*)d_in[4];
    const int*   adj_row  = (const int*)d_in[5];
    const int*   adj_col  = (const int*)d_in[6];
    float*       out      = (float*)d_out;

    cudaFuncSetAttribute(gemm_tc_kernel,
                         cudaFuncAttributeMaxDynamicSharedMemorySize, SMEM_BYTES);

    prep_kernel<<<XBLK + WBLK + RBLK, 256>>>(x, fc_w, adj_row);

    dim3 ggrid(N_HID / BN, (M_NODES + BM - 1) / BM);   // 8 x 79
    gemm_tc_kernel<<<ggrid, 256, SMEM_BYTES>>>();

    spmm_bias_prelu_kernel<<<M_NODES, 128>>>(adj_vals, adj_col, bias, prelu_a, out);
}

// round 9
// speedup vs baseline: 1.0674x; 1.0674x over previous
#include <cuda_runtime.h>
#include <cuda_bf16.h>
#include <cstdint>

#define M_NODES 10000
#define K_IN    512
#define N_HID   512
#define N_EDGES 160000

// Scratch (no allocations allowed)
__device__ float         g_xfts[M_NODES * N_HID];
__device__ __nv_bfloat16 g_xhi[M_NODES * K_IN];
__device__ __nv_bfloat16 g_xlo[M_NODES * K_IN];
__device__ __nv_bfloat16 g_whi[N_HID * K_IN];
__device__ __nv_bfloat16 g_wlo[N_HID * K_IN];
__device__ int           g_rowptr[M_NODES + 1];

// ---------------------------------------------------------------------------
// Fused prep: split X / W (fp32 -> bf16 hi+lo), rowptr.
// ---------------------------------------------------------------------------
#define XBLK 625
#define WBLK 32
#define RBLK 40

__device__ __forceinline__ void split4(float4 v, __nv_bfloat16* hi_arr,
                                       __nv_bfloat16* lo_arr, int i)
{
    __nv_bfloat16 hx = __float2bfloat16_rn(v.x);
    __nv_bfloat16 hy = __float2bfloat16_rn(v.y);
    __nv_bfloat16 hz = __float2bfloat16_rn(v.z);
    __nv_bfloat16 hw = __float2bfloat16_rn(v.w);
    __nv_bfloat16 lx = __float2bfloat16_rn(v.x - __bfloat162float(hx));
    __nv_bfloat16 ly = __float2bfloat16_rn(v.y - __bfloat162float(hy));
    __nv_bfloat16 lz = __float2bfloat16_rn(v.z - __bfloat162float(hz));
    __nv_bfloat16 lw = __float2bfloat16_rn(v.w - __bfloat162float(hw));
    reinterpret_cast<__nv_bfloat162*>(hi_arr)[2 * i]     = __nv_bfloat162(hx, hy);
    reinterpret_cast<__nv_bfloat162*>(hi_arr)[2 * i + 1] = __nv_bfloat162(hz, hw);
    reinterpret_cast<__nv_bfloat162*>(lo_arr)[2 * i]     = __nv_bfloat162(lx, ly);
    reinterpret_cast<__nv_bfloat162*>(lo_arr)[2 * i + 1] = __nv_bfloat162(lz, lw);
}

__global__ __launch_bounds__(256) void prep_kernel(
    const float* __restrict__ x,
    const float* __restrict__ fc_w,
    const int* __restrict__ adj_row)
{
    const int b = blockIdx.x;
    const int t = threadIdx.x;
    if (b < XBLK) {
        const int i0 = b * 2048 + t;
        float4 v[8];
#pragma unroll
        for (int k = 0; k < 8; k++)
            v[k] = reinterpret_cast<const float4*>(x)[i0 + k * 256];
#pragma unroll
        for (int k = 0; k < 8; k++)
            split4(v[k], g_xhi, g_xlo, i0 + k * 256);
    } else if (b < XBLK + WBLK) {
        const int i0 = (b - XBLK) * 2048 + t;
        float4 v[8];
#pragma unroll
        for (int k = 0; k < 8; k++)
            v[k] = reinterpret_cast<const float4*>(fc_w)[i0 + k * 256];
#pragma unroll
        for (int k = 0; k < 8; k++)
            split4(v[k], g_whi, g_wlo, i0 + k * 256);
    } else {
        int r = (b - XBLK - WBLK) * 256 + t;
        if (r > M_NODES) return;
        int lo = 0, hi = N_EDGES;
        while (lo < hi) {
            int mid = (lo + hi) >> 1;
            if (adj_row[mid] < r) lo = mid + 1; else hi = mid;
        }
        g_rowptr[r] = lo;
    }
}

// ---------------------------------------------------------------------------
// Tensor-core GEMM (mma.sync bf16, 3-term split), ldmatrix fragment loads.
// CTA 128x128, BK=32, 256 threads = 8 warps (2m x 4n), warp tile 64x32.
// cp.async double buffer; 40KB/stage -> 2 CTAs/SM.
// ---------------------------------------------------------------------------
#define BM 128
#define BN 128
#define BK 32
#define KSTRIDE 40                        // bf16 per smem row (32 + 8 pad)
#define A_HI_E   0
#define A_LO_E   5120                     // 128*40
#define B_HI_E   10240
#define B_LO_E   15360
#define STAGE_E  20480                    // elems per stage
#define SMEM_BYTES (2 * STAGE_E * 2)      // 81920

__device__ __forceinline__ void cp_async16(uint32_t dst, const void* src, bool pred)
{
    int sz = pred ? 16 : 0;
    asm volatile("cp.async.cg.shared.global [%0], [%1], 16, %2;\n"
                 :: "r"(dst), "l"(src), "r"(sz));
}
__device__ __forceinline__ void cp_commit() { asm volatile("cp.async.commit_group;\n"); }
__device__ __forceinline__ void cp_wait0()  { asm volatile("cp.async.wait_group 0;\n"); }

#define LDSM_X4(r0, r1, r2, r3, addr) \
    asm volatile("ldmatrix.sync.aligned.m8n8.x4.shared.b16 {%0,%1,%2,%3}, [%4];" \
                 : "=r"(r0), "=r"(r1), "=r"(r2), "=r"(r3) : "r"(addr))

__device__ __forceinline__ void mma_bf16(float c[4], const uint32_t a[4],
                                         const uint32_t b[2])
{
    asm volatile(
        "mma.sync.aligned.m16n8k16.row.col.f32.bf16.bf16.f32 "
        "{%0,%1,%2,%3}, {%4,%5,%6,%7}, {%8,%9}, {%0,%1,%2,%3};\n"
        : "+f"(c[0]), "+f"(c[1]), "+f"(c[2]), "+f"(c[3])
        : "r"(a[0]), "r"(a[1]), "r"(a[2]), "r"(a[3]), "r"(b[0]), "r"(b[1]));
}

__global__ __launch_bounds__(256, 2) void gemm_tc_kernel()
{
    extern __shared__ __nv_bfloat16 smem[];
    const int tid  = threadIdx.x;
    const int lane = tid & 31;
    const int wid  = tid >> 5;            // 0..7
    const int wm   = (wid & 1) * 64;      // 2 warps over M
    const int wn   = (wid >> 1) * 32;     // 4 warps over N
    const int m0   = blockIdx.y * BM;
    const int n0   = blockIdx.x * BN;
    const int grp  = lane >> 2;           // 0..7
    const int tig  = lane & 3;            // 0..3

    const uint32_t smem_u32 = (uint32_t)__cvta_generic_to_shared(smem);

    float acc[4][4][4];
#pragma unroll
    for (int mi = 0; mi < 4; mi++)
#pragma unroll
        for (int ni = 0; ni < 4; ni++)
#pragma unroll
            for (int q = 0; q < 4; q++) acc[mi][ni][q] = 0.f;

    // --- loader: 512 (row, chunk) tasks for A and for B; 2 each per thread ---
    auto load_tile = [&](int buf, int k0) {
        uint32_t sbase = smem_u32 + (uint32_t)(buf * STAGE_E) * 2;
#pragma unroll
        for (int rep = 0; rep < 2; rep++) {
            int task = tid + rep * 256;   // 0..511
            int row  = task >> 2;         // 0..127
            int ch   = task & 3;          // 0..3 (16B chunks of 64B row)
            // A
            int gm = m0 + row;
            bool p = (gm < M_NODES);
            int gms = p ? gm : 0;
            uint32_t dA = sbase + (uint32_t)(row * KSTRIDE + ch * 8) * 2;
            cp_async16(dA,                 &g_xhi[(size_t)gms * K_IN + k0 + ch * 8], p);
            cp_async16(dA + A_LO_E * 2,    &g_xlo[(size_t)gms * K_IN + k0 + ch * 8], p);
            // B (row < 128, n0 + row < 512 always)
            int gn = n0 + row;
            uint32_t dB = sbase + (uint32_t)(B_HI_E + row * KSTRIDE + ch * 8) * 2;
            cp_async16(dB,                          &g_whi[(size_t)gn * K_IN + k0 + ch * 8], true);
            cp_async16(dB + (B_LO_E - B_HI_E) * 2,  &g_wlo[(size_t)gn * K_IN + k0 + ch * 8], true);
        }
        cp_commit();
    };

    load_tile(0, 0);

    // ldmatrix per-lane address components (same mapping verified in R7)
    const int a_row = wm + ((lane >> 3) & 1) * 8 + (lane & 7);
    const int a_seg = (lane >> 4) * 8;
    const int b_row = wn + (lane >> 4) * 8 + (lane & 7);
    const int b_seg = ((lane >> 3) & 1) * 8;

    const int NT = K_IN / BK;             // 16
    for (int t = 0; t < NT; t++) {
        cp_wait0();
        __syncthreads();                  // single barrier per K-tile
        if (t + 1 < NT) load_tile((t + 1) & 1, (t + 1) * BK);

        const uint32_t sbase = smem_u32 + (uint32_t)((t & 1) * STAGE_E) * 2;

#pragma unroll
        for (int ks = 0; ks < 2; ks++) {
            const int kcol = ks * 16;

            uint32_t ahi[4][4];
#pragma unroll
            for (int mi = 0; mi < 4; mi++) {
                uint32_t addr = sbase + (uint32_t)((a_row + mi * 16) * KSTRIDE + a_seg + kcol) * 2;
                LDSM_X4(ahi[mi][0], ahi[mi][1], ahi[mi][2], ahi[mi][3], addr);
            }
            uint32_t bhi[4][2], blo[4][2];
#pragma unroll
            for (int njp = 0; njp < 2; njp++) {
                uint32_t addr = sbase + (uint32_t)(B_HI_E + (b_row + njp * 16) * KSTRIDE + b_seg + kcol) * 2;
                LDSM_X4(bhi[njp * 2][0], bhi[njp * 2][1],
                        bhi[njp * 2 + 1][0], bhi[njp * 2 + 1][1], addr);
                LDSM_X4(blo[njp * 2][0], blo[njp * 2][1],
                        blo[njp * 2 + 1][0], blo[njp * 2 + 1][1], addr + (B_LO_E - B_HI_E) * 2);
            }

            // term 1: hi*hi (16 independent MMAs)
#pragma unroll
            for (int mi = 0; mi < 4; mi++)
#pragma unroll
                for (int nj = 0; nj < 4; nj++)
                    mma_bf16(acc[mi][nj], ahi[mi], bhi[nj]);
            // term 2: hi*lo
#pragma unroll
            for (int mi = 0; mi < 4; mi++)
#pragma unroll
                for (int nj = 0; nj < 4; nj++)
                    mma_bf16(acc[mi][nj], ahi[mi], blo[nj]);
            // term 3: lo*hi (load alo late; blo now dead)
            uint32_t alo[4][4];
#pragma unroll
            for (int mi = 0; mi < 4; mi++) {
                uint32_t addr = sbase + (uint32_t)(A_LO_E + (a_row + mi * 16) * KSTRIDE + a_seg + kcol) * 2;
                LDSM_X4(alo[mi][0], alo[mi][1], alo[mi][2], alo[mi][3], addr);
            }
#pragma unroll
            for (int mi = 0; mi < 4; mi++)
#pragma unroll
                for (int nj = 0; nj < 4; nj++)
                    mma_bf16(acc[mi][nj], alo[mi], bhi[nj]);
        }
    }

    // --- epilogue ---
#pragma unroll
    for (int mi = 0; mi < 4; mi++) {
        int gm = m0 + wm + mi * 16 + grp;
#pragma unroll
        for (int nj = 0; nj < 4; nj++) {
            int gn = n0 + wn + nj * 8 + tig * 2;
            if (gm < M_NODES)
                *(float2*)&g_xfts[(size_t)gm * N_HID + gn] =
                    make_float2(acc[mi][nj][0], acc[mi][nj][1]);
            if (gm + 8 < M_NODES)
                *(float2*)&g_xfts[(size_t)(gm + 8) * N_HID + gn] =
                    make_float2(acc[mi][nj][2], acc[mi][nj][3]);
        }
    }
}

// ---------------------------------------------------------------------------
// SPMM + bias + PReLU (rowptr precomputed, 4-deep MLP)
// ---------------------------------------------------------------------------
__global__ __launch_bounds__(128) void spmm_bias_prelu_kernel(
    const float* __restrict__ adj_vals,
    const int* __restrict__ adj_col,
    const float* __restrict__ bias,
    const float* __restrict__ prelu_a,
    float* __restrict__ out)
{
    const int r = blockIdx.x;
    const int c = threadIdx.x * 4;
    const int start = g_rowptr[r];
    const int end   = g_rowptr[r + 1];

    float4 a0 = make_float4(0.f, 0.f, 0.f, 0.f);
    float4 a1 = make_float4(0.f, 0.f, 0.f, 0.f);
    float4 a2 = make_float4(0.f, 0.f, 0.f, 0.f);
    float4 a3 = make_float4(0.f, 0.f, 0.f, 0.f);

    int e = start;
    for (; e + 3 < end; e += 4) {
        const float v0 = __ldg(&adj_vals[e]);
        const float v1 = __ldg(&adj_vals[e + 1]);
        const float v2 = __ldg(&adj_vals[e + 2]);
        const float v3 = __ldg(&adj_vals[e + 3]);
        const int   c0 = __ldg(&adj_col[e]);
        const int   c1 = __ldg(&adj_col[e + 1]);
        const int   c2 = __ldg(&adj_col[e + 2]);
        const int   c3 = __ldg(&adj_col[e + 3]);
        const float4 f0 = *reinterpret_cast<const float4*>(&g_xfts[(size_t)c0 * N_HID + c]);
        const float4 f1 = *reinterpret_cast<const float4*>(&g_xfts[(size_t)c1 * N_HID + c]);
        const float4 f2 = *reinterpret_cast<const float4*>(&g_xfts[(size_t)c2 * N_HID + c]);
        const float4 f3 = *reinterpret_cast<const float4*>(&g_xfts[(size_t)c3 * N_HID + c]);
        a0.x += v0 * f0.x; a0.y += v0 * f0.y; a0.z += v0 * f0.z; a0.w += v0 * f0.w;
        a1.x += v1 * f1.x; a1.y += v1 * f1.y; a1.z += v1 * f1.z; a1.w += v1 * f1.w;
        a2.x += v2 * f2.x; a2.y += v2 * f2.y; a2.z += v2 * f2.z; a2.w += v2 * f2.w;
        a3.x += v3 * f3.x; a3.y += v3 * f3.y; a3.z += v3 * f3.z; a3.w += v3 * f3.w;
    }
    for (; e < end; e++) {
        const float v0 = __ldg(&adj_vals[e]);
        const int   c0 = __ldg(&adj_col[e]);
        const float4 f0 = *reinterpret_cast<const float4*>(&g_xfts[(size_t)c0 * N_HID + c]);
        a0.x += v0 * f0.x; a0.y += v0 * f0.y; a0.z += v0 * f0.z; a0.w += v0 * f0.w;
    }

    const float4 b4 = *reinterpret_cast<const float4*>(&bias[c]);
    const float a = *prelu_a;
    float4 o;
    o.x = (a0.x + a1.x) + (a2.x + a3.x) + b4.x;
    o.y = (a0.y + a1.y) + (a2.y + a3.y) + b4.y;
    o.z = (a0.z + a1.z) + (a2.z + a3.z) + b4.z;
    o.w = (a0.w + a1.w) + (a2.w + a3.w) + b4.w;
    o.x = (o.x >= 0.f) ? o.x : a * o.x;
    o.y = (o.y >= 0.f) ? o.y : a * o.y;
    o.z = (o.z >= 0.f) ? o.z : a * o.z;
    o.w = (o.w >= 0.f) ? o.w : a * o.w;
    *reinterpret_cast<float4*>(&out[(size_t)r * N_HID + c]) = o;
}

extern "C" void kernel_launch(void* const* d_in, const int* in_sizes, int n_in,
                              void* d_out, int out_size)
{
    const float* x        = (const float*)d_in[0];
    const float* fc_w     = (const float*)d_in[1];
    const float* bias     = (const float*)d_in[2];
    const float* prelu_a  = (const float*)d_in[3];
    const float* adj_vals = (const float*)d_in[4];
    const int*   adj_row  = (const int*)d_in[5];
    const int*   adj_col  = (const int*)d_in[6];
    float*       out      = (float*)d_out;

    cudaFuncSetAttribute(gemm_tc_kernel,
                         cudaFuncAttributeMaxDynamicSharedMemorySize, SMEM_BYTES);

    prep_kernel<<<XBLK + WBLK + RBLK, 256>>>(x, fc_w, adj_row);

    dim3 ggrid(N_HID / BN, (M_NODES + BM - 1) / BM);   // 4 x 79
    gemm_tc_kernel<<<ggrid, 256, SMEM_BYTES>>>();

    spmm_bias_prelu_kernel<<<M_NODES, 128>>>(adj_vals, adj_col, bias, prelu_a, out);
}

// round 10
// speedup vs baseline: 1.0884x; 1.0197x over previous
#include <cuda_runtime.h>
#include <cuda_bf16.h>
#include <cstdint>

#define M_NODES 10000
#define K_IN    512
#define N_HID   512
#define N_EDGES 160000

// Scratch (no allocations allowed)
__device__ float         g_xfts[M_NODES * N_HID];
__device__ __nv_bfloat16 g_whi[N_HID * K_IN];
__device__ __nv_bfloat16 g_wlo[N_HID * K_IN];
__device__ int           g_rowptr[M_NODES + 1];

// ---------------------------------------------------------------------------
// Prep: split W (fp32 -> bf16 hi+lo) + rowptr.  X split happens inside GEMM.
//   W: 65,536 float4s -> 32 blocks * 2048
// ---------------------------------------------------------------------------
#define WBLK 32
#define RBLK 40

__device__ __forceinline__ void split4(float4 v, __nv_bfloat16* hi_arr,
                                       __nv_bfloat16* lo_arr, int i)
{
    __nv_bfloat16 hx = __float2bfloat16_rn(v.x);
    __nv_bfloat16 hy = __float2bfloat16_rn(v.y);
    __nv_bfloat16 hz = __float2bfloat16_rn(v.z);
    __nv_bfloat16 hw = __float2bfloat16_rn(v.w);
    __nv_bfloat16 lx = __float2bfloat16_rn(v.x - __bfloat162float(hx));
    __nv_bfloat16 ly = __float2bfloat16_rn(v.y - __bfloat162float(hy));
    __nv_bfloat16 lz = __float2bfloat16_rn(v.z - __bfloat162float(hz));
    __nv_bfloat16 lw = __float2bfloat16_rn(v.w - __bfloat162float(hw));
    reinterpret_cast<__nv_bfloat162*>(hi_arr)[2 * i]     = __nv_bfloat162(hx, hy);
    reinterpret_cast<__nv_bfloat162*>(hi_arr)[2 * i + 1] = __nv_bfloat162(hz, hw);
    reinterpret_cast<__nv_bfloat162*>(lo_arr)[2 * i]     = __nv_bfloat162(lx, ly);
    reinterpret_cast<__nv_bfloat162*>(lo_arr)[2 * i + 1] = __nv_bfloat162(lz, lw);
}

__global__ __launch_bounds__(256) void prep_kernel(
    const float* __restrict__ fc_w,
    const int* __restrict__ adj_row)
{
    const int b = blockIdx.x;
    const int t = threadIdx.x;
    if (b < WBLK) {
        const int i0 = b * 2048 + t;
        float4 v[8];
#pragma unroll
        for (int k = 0; k < 8; k++)
            v[k] = reinterpret_cast<const float4*>(fc_w)[i0 + k * 256];
#pragma unroll
        for (int k = 0; k < 8; k++)
            split4(v[k], g_whi, g_wlo, i0 + k * 256);
    } else {
        int r = (b - WBLK) * 256 + t;
        if (r > M_NODES) return;
        int lo = 0, hi = N_EDGES;
        while (lo < hi) {
            int mid = (lo + hi) >> 1;
            if (adj_row[mid] < r) lo = mid + 1; else hi = mid;
        }
        g_rowptr[r] = lo;
    }
}

// ---------------------------------------------------------------------------
// Tensor-core GEMM (mma.sync bf16, 3-term split), in-kernel A split.
// CTA 128x128, BK=32, 256 threads = 8 warps (2m x 4n), warp tile 64x32.
// A: fp32 LDG register-prefetch -> convert -> STS double buffer.
// B: cp.async double buffer from pre-split g_whi/g_wlo.
// ---------------------------------------------------------------------------
#define BM 128
#define BN 128
#define BK 32
#define KSTRIDE 40                        // bf16 per smem row (32 + 8 pad)
#define A_HI_E   0
#define A_LO_E   5120                     // 128*40
#define B_HI_E   10240
#define B_LO_E   15360
#define STAGE_E  20480                    // elems per stage
#define SMEM_BYTES (2 * STAGE_E * 2)      // 81920 -> 2 CTAs/SM (smem-limited)

__device__ __forceinline__ void cp_async16(uint32_t dst, const void* src)
{
    asm volatile("cp.async.cg.shared.global [%0], [%1], 16;\n"
                 :: "r"(dst), "l"(src));
}
__device__ __forceinline__ void cp_commit() { asm volatile("cp.async.commit_group;\n"); }
__device__ __forceinline__ void cp_wait0()  { asm volatile("cp.async.wait_group 0;\n"); }

#define LDSM_X4(r0, r1, r2, r3, addr) \
    asm volatile("ldmatrix.sync.aligned.m8n8.x4.shared.b16 {%0,%1,%2,%3}, [%4];" \
                 : "=r"(r0), "=r"(r1), "=r"(r2), "=r"(r3) : "r"(addr))

#define STS128(addr, r0, r1, r2, r3) \
    asm volatile("st.shared.v4.b32 [%0], {%1,%2,%3,%4};" \
                 :: "r"(addr), "r"(r0), "r"(r1), "r"(r2), "r"(r3) : "memory")

__device__ __forceinline__ void mma_bf16(float c[4], const uint32_t a[4],
                                         const uint32_t b[2])
{
    asm volatile(
        "mma.sync.aligned.m16n8k16.row.col.f32.bf16.bf16.f32 "
        "{%0,%1,%2,%3}, {%4,%5,%6,%7}, {%8,%9}, {%0,%1,%2,%3};\n"
        : "+f"(c[0]), "+f"(c[1]), "+f"(c[2]), "+f"(c[3])
        : "r"(a[0]), "r"(a[1]), "r"(a[2]), "r"(a[3]), "r"(b[0]), "r"(b[1]));
}

__device__ __forceinline__ uint32_t pack_bf2(__nv_bfloat16 a, __nv_bfloat16 b)
{
    __nv_bfloat162 t(a, b);
    return *reinterpret_cast<uint32_t*>(&t);
}

__global__ __launch_bounds__(256) void gemm_tc_kernel(const float* __restrict__ X)
{
    extern __shared__ __nv_bfloat16 smem[];
    const int tid  = threadIdx.x;
    const int lane = tid & 31;
    const int wid  = tid >> 5;            // 0..7
    const int wm   = (wid & 1) * 64;      // 2 warps over M
    const int wn   = (wid >> 1) * 32;     // 4 warps over N
    const int m0   = blockIdx.y * BM;
    const int n0   = blockIdx.x * BN;
    const int grp  = lane >> 2;           // 0..7
    const int tig  = lane & 3;            // 0..3

    const uint32_t smem_u32 = (uint32_t)__cvta_generic_to_shared(smem);

    float acc[4][4][4];
#pragma unroll
    for (int mi = 0; mi < 4; mi++)
#pragma unroll
        for (int ni = 0; ni < 4; ni++)
#pragma unroll
            for (int q = 0; q < 4; q++) acc[mi][ni][q] = 0.f;

    // --- A loader: thread -> (row = tid>>1, half = tid&1), 16 fp32 per tile ---
    const int rowA  = tid >> 1;
    const int halfA = tid & 1;
    int gmA = m0 + rowA;
    if (gmA >= M_NODES) gmA = 0;          // clamp; epilogue discards these rows
    const float* Xrow = X + (size_t)gmA * K_IN + halfA * 16;

    auto ldg_A = [&](int k0, float4 v[4]) {
        const float4* p = reinterpret_cast<const float4*>(Xrow + k0);
        v[0] = __ldg(p);
        v[1] = __ldg(p + 1);
        v[2] = __ldg(p + 2);
        v[3] = __ldg(p + 3);
    };

    auto sts_A = [&](int buf, const float4 v[4]) {
        uint32_t hi[8], lo[8];
#pragma unroll
        for (int j = 0; j < 4; j++) {
            __nv_bfloat16 hx = __float2bfloat16_rn(v[j].x);
            __nv_bfloat16 hy = __float2bfloat16_rn(v[j].y);
            __nv_bfloat16 hz = __float2bfloat16_rn(v[j].z);
            __nv_bfloat16 hw = __float2bfloat16_rn(v[j].w);
            hi[2 * j]     = pack_bf2(hx, hy);
            hi[2 * j + 1] = pack_bf2(hz, hw);
            lo[2 * j]     = pack_bf2(__float2bfloat16_rn(v[j].x - __bfloat162float(hx)),
                                     __float2bfloat16_rn(v[j].y - __bfloat162float(hy)));
            lo[2 * j + 1] = pack_bf2(__float2bfloat16_rn(v[j].z - __bfloat162float(hz)),
                                     __float2bfloat16_rn(v[j].w - __bfloat162float(hw)));
        }
        uint32_t base = smem_u32 +
            (uint32_t)(buf * STAGE_E + rowA * KSTRIDE + halfA * 16) * 2;
        STS128(base,      hi[0], hi[1], hi[2], hi[3]);
        STS128(base + 16, hi[4], hi[5], hi[6], hi[7]);
        uint32_t basel = base + A_LO_E * 2;
        STS128(basel,      lo[0], lo[1], lo[2], lo[3]);
        STS128(basel + 16, lo[4], lo[5], lo[6], lo[7]);
    };

    // --- B loader: 512 (row, chunk) tasks, 2 per thread ---
    auto load_B = [&](int buf, int k0) {
        uint32_t sbase = smem_u32 + (uint32_t)(buf * STAGE_E) * 2;
#pragma unroll
        for (int rep = 0; rep < 2; rep++) {
            int task = tid + rep * 256;   // 0..511
            int row  = task >> 2;         // 0..127
            int ch   = task & 3;          // 0..3
            int gn   = n0 + row;          // < 512 always
            uint32_t dB = sbase + (uint32_t)(B_HI_E + row * KSTRIDE + ch * 8) * 2;
            cp_async16(dB,                         &g_whi[(size_t)gn * K_IN + k0 + ch * 8]);
            cp_async16(dB + (B_LO_E - B_HI_E) * 2, &g_wlo[(size_t)gn * K_IN + k0 + ch * 8]);
        }
        cp_commit();
    };

    // --- prologue ---
    float4 av[4];
    ldg_A(0, av);
    load_B(0, 0);
    sts_A(0, av);
    ldg_A(BK, av);                        // prefetch tile 1

    // ldmatrix per-lane address components
    const int a_row = wm + ((lane >> 3) & 1) * 8 + (lane & 7);
    const int a_seg = (lane >> 4) * 8;
    const int b_row = wn + (lane >> 4) * 8 + (lane & 7);
    const int b_seg = ((lane >> 3) & 1) * 8;

    const int NT = K_IN / BK;             // 16
    for (int t = 0; t < NT; t++) {
        cp_wait0();
        __syncthreads();                  // single barrier per K-tile

        if (t + 1 < NT) {
            sts_A((t + 1) & 1, av);       // A tile t+1 (safe: buffer free since barrier)
            load_B((t + 1) & 1, (t + 1) * BK);
            if (t + 2 < NT) ldg_A((t + 2) * BK, av);
        }

        const uint32_t sbase = smem_u32 + (uint32_t)((t & 1) * STAGE_E) * 2;

#pragma unroll
        for (int ks = 0; ks < 2; ks++) {
            const int kcol = ks * 16;

            uint32_t ahi[4][4];
#pragma unroll
            for (int mi = 0; mi < 4; mi++) {
                uint32_t addr = sbase + (uint32_t)((a_row + mi * 16) * KSTRIDE + a_seg + kcol) * 2;
                LDSM_X4(ahi[mi][0], ahi[mi][1], ahi[mi][2], ahi[mi][3], addr);
            }
            uint32_t bhi[4][2], blo[4][2];
#pragma unroll
            for (int njp = 0; njp < 2; njp++) {
                uint32_t addr = sbase + (uint32_t)(B_HI_E + (b_row + njp * 16) * KSTRIDE + b_seg + kcol) * 2;
                LDSM_X4(bhi[njp * 2][0], bhi[njp * 2][1],
                        bhi[njp * 2 + 1][0], bhi[njp * 2 + 1][1], addr);
                LDSM_X4(blo[njp * 2][0], blo[njp * 2][1],
                        blo[njp * 2 + 1][0], blo[njp * 2 + 1][1], addr + (B_LO_E - B_HI_E) * 2);
            }

            // term 1: hi*hi
#pragma unroll
            for (int mi = 0; mi < 4; mi++)
#pragma unroll
                for (int nj = 0; nj < 4; nj++)
                    mma_bf16(acc[mi][nj], ahi[mi], bhi[nj]);
            // term 2: hi*lo
#pragma unroll
            for (int mi = 0; mi < 4; mi++)
#pragma unroll
                for (int nj = 0; nj < 4; nj++)
                    mma_bf16(acc[mi][nj], ahi[mi], blo[nj]);
            // term 3: lo*hi (load alo late; blo dead)
            uint32_t alo[4][4];
#pragma unroll
            for (int mi = 0; mi < 4; mi++) {
                uint32_t addr = sbase + (uint32_t)(A_LO_E + (a_row + mi * 16) * KSTRIDE + a_seg + kcol) * 2;
                LDSM_X4(alo[mi][0], alo[mi][1], alo[mi][2], alo[mi][3], addr);
            }
#pragma unroll
            for (int mi = 0; mi < 4; mi++)
#pragma unroll
                for (int nj = 0; nj < 4; nj++)
                    mma_bf16(acc[mi][nj], alo[mi], bhi[nj]);
        }
    }

    // --- epilogue ---
#pragma unroll
    for (int mi = 0; mi < 4; mi++) {
        int gm = m0 + wm + mi * 16 + grp;
#pragma unroll
        for (int nj = 0; nj < 4; nj++) {
            int gn = n0 + wn + nj * 8 + tig * 2;
            if (gm < M_NODES)
                *(float2*)&g_xfts[(size_t)gm * N_HID + gn] =
                    make_float2(acc[mi][nj][0], acc[mi][nj][1]);
            if (gm + 8 < M_NODES)
                *(float2*)&g_xfts[(size_t)(gm + 8) * N_HID + gn] =
                    make_float2(acc[mi][nj][2], acc[mi][nj][3]);
        }
    }
}

// ---------------------------------------------------------------------------
// SPMM + bias + PReLU (rowptr precomputed, 4-deep MLP)
// ---------------------------------------------------------------------------
__global__ __launch_bounds__(128) void spmm_bias_prelu_kernel(
    const float* __restrict__ adj_vals,
    const int* __restrict__ adj_col,
    const float* __restrict__ bias,
    const float* __restrict__ prelu_a,
    float* __restrict__ out)
{
    const int r = blockIdx.x;
    const int c = threadIdx.x * 4;
    const int start = g_rowptr[r];
    const int end   = g_rowptr[r + 1];

    float4 a0 = make_float4(0.f, 0.f, 0.f, 0.f);
    float4 a1 = make_float4(0.f, 0.f, 0.f, 0.f);
    float4 a2 = make_float4(0.f, 0.f, 0.f, 0.f);
    float4 a3 = make_float4(0.f, 0.f, 0.f, 0.f);

    int e = start;
    for (; e + 3 < end; e += 4) {
        const float v0 = __ldg(&adj_vals[e]);
        const float v1 = __ldg(&adj_vals[e + 1]);
        const float v2 = __ldg(&adj_vals[e + 2]);
        const float v3 = __ldg(&adj_vals[e + 3]);
        const int   c0 = __ldg(&adj_col[e]);
        const int   c1 = __ldg(&adj_col[e + 1]);
        const int   c2 = __ldg(&adj_col[e + 2]);
        const int   c3 = __ldg(&adj_col[e + 3]);
        const float4 f0 = *reinterpret_cast<const float4*>(&g_xfts[(size_t)c0 * N_HID + c]);
        const float4 f1 = *reinterpret_cast<const float4*>(&g_xfts[(size_t)c1 * N_HID + c]);
        const float4 f2 = *reinterpret_cast<const float4*>(&g_xfts[(size_t)c2 * N_HID + c]);
        const float4 f3 = *reinterpret_cast<const float4*>(&g_xfts[(size_t)c3 * N_HID + c]);
        a0.x += v0 * f0.x; a0.y += v0 * f0.y; a0.z += v0 * f0.z; a0.w += v0 * f0.w;
        a1.x += v1 * f1.x; a1.y += v1 * f1.y; a1.z += v1 * f1.z; a1.w += v1 * f1.w;
        a2.x += v2 * f2.x; a2.y += v2 * f2.y; a2.z += v2 * f2.z; a2.w += v2 * f2.w;
        a3.x += v3 * f3.x; a3.y += v3 * f3.y; a3.z += v3 * f3.z; a3.w += v3 * f3.w;
    }
    for (; e < end; e++) {
        const float v0 = __ldg(&adj_vals[e]);
        const int   c0 = __ldg(&adj_col[e]);
        const float4 f0 = *reinterpret_cast<const float4*>(&g_xfts[(size_t)c0 * N_HID + c]);
        a0.x += v0 * f0.x; a0.y += v0 * f0.y; a0.z += v0 * f0.z; a0.w += v0 * f0.w;
    }

    const float4 b4 = *reinterpret_cast<const float4*>(&bias[c]);
    const float a = *prelu_a;
    float4 o;
    o.x = (a0.x + a1.x) + (a2.x + a3.x) + b4.x;
    o.y = (a0.y + a1.y) + (a2.y + a3.y) + b4.y;
    o.z = (a0.z + a1.z) + (a2.z + a3.z) + b4.z;
    o.w = (a0.w + a1.w) + (a2.w + a3.w) + b4.w;
    o.x = (o.x >= 0.f) ? o.x : a * o.x;
    o.y = (o.y >= 0.f) ? o.y : a * o.y;
    o.z = (o.z >= 0.f) ? o.z : a * o.z;
    o.w = (o.w >= 0.f) ? o.w : a * o.w;
    *reinterpret_cast<float4*>(&out[(size_t)r * N_HID + c]) = o;
}

extern "C" void kernel_launch(void* const* d_in, const int* in_sizes, int n_in,
                              void* d_out, int out_size)
{
    const float* x        = (const float*)d_in[0];
    const float* fc_w     = (const float*)d_in[1];
    const float* bias     = (const float*)d_in[2];
    const float* prelu_a  = (const float*)d_in[3];
    const float* adj_vals = (const float*)d_in[4];
    const int*   adj_row  = (const int*)d_in[5];
    const int*   adj_col  = (const int*)d_in[6];
    float*       out      = (float*)d_out;

    cudaFuncSetAttribute(gemm_tc_kernel,
                         cudaFuncAttributeMaxDynamicSharedMemorySize, SMEM_BYTES);

    prep_kernel<<<WBLK + RBLK, 256>>>(fc_w, adj_row);

    dim3 ggrid(N_HID / BN, (M_NODES + BM - 1) / BM);   // 4 x 79
    gemm_tc_kernel<<<ggrid, 256, SMEM_BYTES>>>(x);

    spmm_bias_prelu_kernel<<<M_NODES, 128>>>(adj_vals, adj_col, bias, prelu_a, out);
}

// round 11
// speedup vs baseline: 1.1551x; 1.0613x over previous
#include <cuda_runtime.h>
#include <cuda_bf16.h>
#include <cuda_fp16.h>
#include <cstdint>

#define M_NODES 10000
#define K_IN    512
#define N_HID   512
#define N_EDGES 160000

// Scratch (no allocations allowed)
__device__ __half        g_xfts_h[M_NODES * N_HID];   // fp16 x_fts (halves SPMM bytes)
__device__ __nv_bfloat16 g_whi[N_HID * K_IN];
__device__ __nv_bfloat16 g_wlo[N_HID * K_IN];
__device__ int           g_rowptr[M_NODES + 1];

// ---------------------------------------------------------------------------
// Prep: split W (fp32 -> bf16 hi+lo) + rowptr via edge-parallel scatter.
//   W:       32 blocks * 256 thr * 8 float4
//   rowptr: 626 blocks (160001 virtual edge slots)
// ---------------------------------------------------------------------------
#define WBLK 32
#define RPBLK 626

__device__ __forceinline__ void split4(float4 v, __nv_bfloat16* hi_arr,
                                       __nv_bfloat16* lo_arr, int i)
{
    __nv_bfloat16 hx = __float2bfloat16_rn(v.x);
    __nv_bfloat16 hy = __float2bfloat16_rn(v.y);
    __nv_bfloat16 hz = __float2bfloat16_rn(v.z);
    __nv_bfloat16 hw = __float2bfloat16_rn(v.w);
    __nv_bfloat16 lx = __float2bfloat16_rn(v.x - __bfloat162float(hx));
    __nv_bfloat16 ly = __float2bfloat16_rn(v.y - __bfloat162float(hy));
    __nv_bfloat16 lz = __float2bfloat16_rn(v.z - __bfloat162float(hz));
    __nv_bfloat16 lw = __float2bfloat16_rn(v.w - __bfloat162float(hw));
    reinterpret_cast<__nv_bfloat162*>(hi_arr)[2 * i]     = __nv_bfloat162(hx, hy);
    reinterpret_cast<__nv_bfloat162*>(hi_arr)[2 * i + 1] = __nv_bfloat162(hz, hw);
    reinterpret_cast<__nv_bfloat162*>(lo_arr)[2 * i]     = __nv_bfloat162(lx, ly);
    reinterpret_cast<__nv_bfloat162*>(lo_arr)[2 * i + 1] = __nv_bfloat162(lz, lw);
}

__global__ __launch_bounds__(256) void prep_kernel(
    const float* __restrict__ fc_w,
    const int* __restrict__ adj_row)
{
    const int b = blockIdx.x;
    const int t = threadIdx.x;
    if (b < WBLK) {
        const int i0 = b * 2048 + t;
        float4 v[8];
#pragma unroll
        for (int k = 0; k < 8; k++)
            v[k] = reinterpret_cast<const float4*>(fc_w)[i0 + k * 256];
#pragma unroll
        for (int k = 0; k < 8; k++)
            split4(v[k], g_whi, g_wlo, i0 + k * 256);
    } else {
        // rowptr[r] = lower_bound(adj_row, r), computed by scatter:
        // thread e fills rowptr[r] = e for r in (adj_row[e-1], adj_row[e]].
        int e = (b - WBLK) * 256 + t;
        if (e > N_EDGES) return;
        int prev = (e == 0) ? -1 : adj_row[e - 1];
        int cur  = (e == N_EDGES) ? M_NODES : adj_row[e];
        for (int r = prev + 1; r <= cur; r++)
            g_rowptr[r] = e;
        // note: for e < N_EDGES this writes r up to cur == adj_row[e];
        // rowptr[cur] will be overwritten by the FIRST edge of row cur only
        // if e is not the first — but since every thread with the same cur
        // writes e, the smallest-e thread must win. Guard: only the first
        // edge of each row (prev < cur) writes rowptr[cur]; others skip all.
        // (prev == cur => empty loop, so this is already satisfied.)
    }
}

// ---------------------------------------------------------------------------
// Tensor-core GEMM (mma.sync bf16, 3-term split), in-kernel A split.
// CTA 128x128, BK=32, 256 threads = 8 warps (2m x 4n), warp tile 64x32.
// A: fp32 LDG register-prefetch -> convert -> STS double buffer.
// B: cp.async double buffer from pre-split g_whi/g_wlo.
// Epilogue: fp32 acc -> fp16 store.
// ---------------------------------------------------------------------------
#define BM 128
#define BN 128
#define BK 32
#define KSTRIDE 40
#define A_HI_E   0
#define A_LO_E   5120
#define B_HI_E   10240
#define B_LO_E   15360
#define STAGE_E  20480
#define SMEM_BYTES (2 * STAGE_E * 2)      // 81920 -> 2 CTAs/SM

__device__ __forceinline__ void cp_async16(uint32_t dst, const void* src)
{
    asm volatile("cp.async.cg.shared.global [%0], [%1], 16;\n"
                 :: "r"(dst), "l"(src));
}
__device__ __forceinline__ void cp_commit() { asm volatile("cp.async.commit_group;\n"); }
__device__ __forceinline__ void cp_wait0()  { asm volatile("cp.async.wait_group 0;\n"); }

#define LDSM_X4(r0, r1, r2, r3, addr) \
    asm volatile("ldmatrix.sync.aligned.m8n8.x4.shared.b16 {%0,%1,%2,%3}, [%4];" \
                 : "=r"(r0), "=r"(r1), "=r"(r2), "=r"(r3) : "r"(addr))

#define STS128(addr, r0, r1, r2, r3) \
    asm volatile("st.shared.v4.b32 [%0], {%1,%2,%3,%4};" \
                 :: "r"(addr), "r"(r0), "r"(r1), "r"(r2), "r"(r3) : "memory")

__device__ __forceinline__ void mma_bf16(float c[4], const uint32_t a[4],
                                         const uint32_t b[2])
{
    asm volatile(
        "mma.sync.aligned.m16n8k16.row.col.f32.bf16.bf16.f32 "
        "{%0,%1,%2,%3}, {%4,%5,%6,%7}, {%8,%9}, {%0,%1,%2,%3};\n"
        : "+f"(c[0]), "+f"(c[1]), "+f"(c[2]), "+f"(c[3])
        : "r"(a[0]), "r"(a[1]), "r"(a[2]), "r"(a[3]), "r"(b[0]), "r"(b[1]));
}

__device__ __forceinline__ uint32_t pack_bf2(__nv_bfloat16 a, __nv_bfloat16 b)
{
    __nv_bfloat162 t(a, b);
    return *reinterpret_cast<uint32_t*>(&t);
}

__global__ __launch_bounds__(256) void gemm_tc_kernel(const float* __restrict__ X)
{
    extern __shared__ __nv_bfloat16 smem[];
    const int tid  = threadIdx.x;
    const int lane = tid & 31;
    const int wid  = tid >> 5;
    const int wm   = (wid & 1) * 64;
    const int wn   = (wid >> 1) * 32;
    const int m0   = blockIdx.y * BM;
    const int n0   = blockIdx.x * BN;
    const int grp  = lane >> 2;
    const int tig  = lane & 3;

    const uint32_t smem_u32 = (uint32_t)__cvta_generic_to_shared(smem);

    float acc[4][4][4];
#pragma unroll
    for (int mi = 0; mi < 4; mi++)
#pragma unroll
        for (int ni = 0; ni < 4; ni++)
#pragma unroll
            for (int q = 0; q < 4; q++) acc[mi][ni][q] = 0.f;

    const int rowA  = tid >> 1;
    const int halfA = tid & 1;
    int gmA = m0 + rowA;
    if (gmA >= M_NODES) gmA = 0;
    const float* Xrow = X + (size_t)gmA * K_IN + halfA * 16;

    auto ldg_A = [&](int k0, float4 v[4]) {
        const float4* p = reinterpret_cast<const float4*>(Xrow + k0);
        v[0] = __ldg(p);
        v[1] = __ldg(p + 1);
        v[2] = __ldg(p + 2);
        v[3] = __ldg(p + 3);
    };

    auto sts_A = [&](int buf, const float4 v[4]) {
        uint32_t hi[8], lo[8];
#pragma unroll
        for (int j = 0; j < 4; j++) {
            __nv_bfloat16 hx = __float2bfloat16_rn(v[j].x);
            __nv_bfloat16 hy = __float2bfloat16_rn(v[j].y);
            __nv_bfloat16 hz = __float2bfloat16_rn(v[j].z);
            __nv_bfloat16 hw = __float2bfloat16_rn(v[j].w);
            hi[2 * j]     = pack_bf2(hx, hy);
            hi[2 * j + 1] = pack_bf2(hz, hw);
            lo[2 * j]     = pack_bf2(__float2bfloat16_rn(v[j].x - __bfloat162float(hx)),
                                     __float2bfloat16_rn(v[j].y - __bfloat162float(hy)));
            lo[2 * j + 1] = pack_bf2(__float2bfloat16_rn(v[j].z - __bfloat162float(hz)),
                                     __float2bfloat16_rn(v[j].w - __bfloat162float(hw)));
        }
        uint32_t base = smem_u32 +
            (uint32_t)(buf * STAGE_E + rowA * KSTRIDE + halfA * 16) * 2;
        STS128(base,      hi[0], hi[1], hi[2], hi[3]);
        STS128(base + 16, hi[4], hi[5], hi[6], hi[7]);
        uint32_t basel = base + A_LO_E * 2;
        STS128(basel,      lo[0], lo[1], lo[2], lo[3]);
        STS128(basel + 16, lo[4], lo[5], lo[6], lo[7]);
    };

    auto load_B = [&](int buf, int k0) {
        uint32_t sbase = smem_u32 + (uint32_t)(buf * STAGE_E) * 2;
#pragma unroll
        for (int rep = 0; rep < 2; rep++) {
            int task = tid + rep * 256;
            int row  = task >> 2;
            int ch   = task & 3;
            int gn   = n0 + row;
            uint32_t dB = sbase + (uint32_t)(B_HI_E + row * KSTRIDE + ch * 8) * 2;
            cp_async16(dB,                         &g_whi[(size_t)gn * K_IN + k0 + ch * 8]);
            cp_async16(dB + (B_LO_E - B_HI_E) * 2, &g_wlo[(size_t)gn * K_IN + k0 + ch * 8]);
        }
        cp_commit();
    };

    float4 av[4];
    ldg_A(0, av);
    load_B(0, 0);
    sts_A(0, av);
    ldg_A(BK, av);

    const int a_row = wm + ((lane >> 3) & 1) * 8 + (lane & 7);
    const int a_seg = (lane >> 4) * 8;
    const int b_row = wn + (lane >> 4) * 8 + (lane & 7);
    const int b_seg = ((lane >> 3) & 1) * 8;

    const int NT = K_IN / BK;
    for (int t = 0; t < NT; t++) {
        cp_wait0();
        __syncthreads();

        if (t + 1 < NT) {
            sts_A((t + 1) & 1, av);
            load_B((t + 1) & 1, (t + 1) * BK);
            if (t + 2 < NT) ldg_A((t + 2) * BK, av);
        }

        const uint32_t sbase = smem_u32 + (uint32_t)((t & 1) * STAGE_E) * 2;

#pragma unroll
        for (int ks = 0; ks < 2; ks++) {
            const int kcol = ks * 16;

            uint32_t ahi[4][4];
#pragma unroll
            for (int mi = 0; mi < 4; mi++) {
                uint32_t addr = sbase + (uint32_t)((a_row + mi * 16) * KSTRIDE + a_seg + kcol) * 2;
                LDSM_X4(ahi[mi][0], ahi[mi][1], ahi[mi][2], ahi[mi][3], addr);
            }
            uint32_t bhi[4][2], blo[4][2];
#pragma unroll
            for (int njp = 0; njp < 2; njp++) {
                uint32_t addr = sbase + (uint32_t)(B_HI_E + (b_row + njp * 16) * KSTRIDE + b_seg + kcol) * 2;
                LDSM_X4(bhi[njp * 2][0], bhi[njp * 2][1],
                        bhi[njp * 2 + 1][0], bhi[njp * 2 + 1][1], addr);
                LDSM_X4(blo[njp * 2][0], blo[njp * 2][1],
                        blo[njp * 2 + 1][0], blo[njp * 2 + 1][1], addr + (B_LO_E - B_HI_E) * 2);
            }

#pragma unroll
            for (int mi = 0; mi < 4; mi++)
#pragma unroll
                for (int nj = 0; nj < 4; nj++)
                    mma_bf16(acc[mi][nj], ahi[mi], bhi[nj]);
#pragma unroll
            for (int mi = 0; mi < 4; mi++)
#pragma unroll
                for (int nj = 0; nj < 4; nj++)
                    mma_bf16(acc[mi][nj], ahi[mi], blo[nj]);
            uint32_t alo[4][4];
#pragma unroll
            for (int mi = 0; mi < 4; mi++) {
                uint32_t addr = sbase + (uint32_t)(A_LO_E + (a_row + mi * 16) * KSTRIDE + a_seg + kcol) * 2;
                LDSM_X4(alo[mi][0], alo[mi][1], alo[mi][2], alo[mi][3], addr);
            }
#pragma unroll
            for (int mi = 0; mi < 4; mi++)
#pragma unroll
                for (int nj = 0; nj < 4; nj++)
                    mma_bf16(acc[mi][nj], alo[mi], bhi[nj]);
        }
    }

    // --- epilogue: fp32 acc -> fp16 x_fts ---
#pragma unroll
    for (int mi = 0; mi < 4; mi++) {
        int gm = m0 + wm + mi * 16 + grp;
#pragma unroll
        for (int nj = 0; nj < 4; nj++) {
            int gn = n0 + wn + nj * 8 + tig * 2;
            if (gm < M_NODES) {
                __half2 h = __float22half2_rn(make_float2(acc[mi][nj][0], acc[mi][nj][1]));
                *reinterpret_cast<__half2*>(&g_xfts_h[(size_t)gm * N_HID + gn]) = h;
            }
            if (gm + 8 < M_NODES) {
                __half2 h = __float22half2_rn(make_float2(acc[mi][nj][2], acc[mi][nj][3]));
                *reinterpret_cast<__half2*>(&g_xfts_h[(size_t)(gm + 8) * N_HID + gn]) = h;
            }
        }
    }
}

// ---------------------------------------------------------------------------
// SPMM + bias + PReLU: fp16 gathers (8B/thread), fp32 accumulate, 4-deep MLP.
// ---------------------------------------------------------------------------
__global__ __launch_bounds__(128) void spmm_bias_prelu_kernel(
    const float* __restrict__ adj_vals,
    const int* __restrict__ adj_col,
    const float* __restrict__ bias,
    const float* __restrict__ prelu_a,
    float* __restrict__ out)
{
    const int r = blockIdx.x;
    const int c = threadIdx.x * 4;              // half index (4 halves/thread)
    const int start = g_rowptr[r];
    const int end   = g_rowptr[r + 1];

    float4 a0 = make_float4(0.f, 0.f, 0.f, 0.f);
    float4 a1 = make_float4(0.f, 0.f, 0.f, 0.f);
    float4 a2 = make_float4(0.f, 0.f, 0.f, 0.f);
    float4 a3 = make_float4(0.f, 0.f, 0.f, 0.f);

    auto gather = [&](int e) -> float4 {
        const int col = __ldg(&adj_col[e]);
        const __half2* p = reinterpret_cast<const __half2*>(
            &g_xfts_h[(size_t)col * N_HID + c]);
        float2 f0 = __half22float2(p[0]);
        float2 f1 = __half22float2(p[1]);
        return make_float4(f0.x, f0.y, f1.x, f1.y);
    };

    int e = start;
    for (; e + 3 < end; e += 4) {
        const float v0 = __ldg(&adj_vals[e]);
        const float v1 = __ldg(&adj_vals[e + 1]);
        const float v2 = __ldg(&adj_vals[e + 2]);
        const float v3 = __ldg(&adj_vals[e + 3]);
        float4 f0 = gather(e);
        float4 f1 = gather(e + 1);
        float4 f2 = gather(e + 2);
        float4 f3 = gather(e + 3);
        a0.x += v0 * f0.x; a0.y += v0 * f0.y; a0.z += v0 * f0.z; a0.w += v0 * f0.w;
        a1.x += v1 * f1.x; a1.y += v1 * f1.y; a1.z += v1 * f1.z; a1.w += v1 * f1.w;
        a2.x += v2 * f2.x; a2.y += v2 * f2.y; a2.z += v2 * f2.z; a2.w += v2 * f2.w;
        a3.x += v3 * f3.x; a3.y += v3 * f3.y; a3.z += v3 * f3.z; a3.w += v3 * f3.w;
    }
    for (; e < end; e++) {
        const float v0 = __ldg(&adj_vals[e]);
        float4 f0 = gather(e);
        a0.x += v0 * f0.x; a0.y += v0 * f0.y; a0.z += v0 * f0.z; a0.w += v0 * f0.w;
    }

    const float4 b4 = *reinterpret_cast<const float4*>(&bias[c]);
    const float a = *prelu_a;
    float4 o;
    o.x = (a0.x + a1.x) + (a2.x + a3.x) + b4.x;
    o.y = (a0.y + a1.y) + (a2.y + a3.y) + b4.y;
    o.z = (a0.z + a1.z) + (a2.z + a3.z) + b4.z;
    o.w = (a0.w + a1.w) + (a2.w + a3.w) + b4.w;
    o.x = (o.x >= 0.f) ? o.x : a * o.x;
    o.y = (o.y >= 0.f) ? o.y : a * o.y;
    o.z = (o.z >= 0.f) ? o.z : a * o.z;
    o.w = (o.w >= 0.f) ? o.w : a * o.w;
    *reinterpret_cast<float4*>(&out[(size_t)r * N_HID + c]) = o;
}

extern "C" void kernel_launch(void* const* d_in, const int* in_sizes, int n_in,
                              void* d_out, int out_size)
{
    const float* x        = (const float*)d_in[0];
    const float* fc_w     = (const float*)d_in[1];
    const float* bias     = (const float*)d_in[2];
    const float* prelu_a  = (const float*)d_in[3];
    const float* adj_vals = (const float*)d_in[4];
    const int*   adj_row  = (const int*)d_in[5];
    const int*   adj_col  = (const int*)d_in[6];
    float*       out      = (float*)d_out;

    cudaFuncSetAttribute(gemm_tc_kernel,
                         cudaFuncAttributeMaxDynamicSharedMemorySize, SMEM_BYTES);

    prep_kernel<<<WBLK + RPBLK, 256>>>(fc_w, adj_row);

    dim3 ggrid(N_HID / BN, (M_NODES + BM - 1) / BM);   // 4 x 79
    gemm_tc_kernel<<<ggrid, 256, SMEM_BYTES>>>(x);

    spmm_bias_prelu_kernel<<<M_NODES, 128>>>(adj_vals, adj_col, bias, prelu_a, out);
}

// round 12
// speedup vs baseline: 1.1858x; 1.0265x over previous
#include <cuda_runtime.h>
#include <cuda_bf16.h>
#include <cuda_fp16.h>
#include <cstdint>

#define M_NODES 10000
#define K_IN    512
#define N_HID   512
#define N_EDGES 160000

// Scratch (no allocations allowed)
__device__ __half        g_xfts_h[M_NODES * N_HID];   // fp16 x_fts (L2-resident, 10 MB)
__device__ __nv_bfloat16 g_whi[N_HID * K_IN];
__device__ __nv_bfloat16 g_wlo[N_HID * K_IN];
__device__ int           g_rowptr[M_NODES + 1];

// ---------------------------------------------------------------------------
// Prep: split W (fp32 -> bf16 hi+lo) + rowptr via edge-parallel scatter.
// ---------------------------------------------------------------------------
#define WBLK 32
#define RPBLK 626

__device__ __forceinline__ void split4(float4 v, __nv_bfloat16* hi_arr,
                                       __nv_bfloat16* lo_arr, int i)
{
    __nv_bfloat16 hx = __float2bfloat16_rn(v.x);
    __nv_bfloat16 hy = __float2bfloat16_rn(v.y);
    __nv_bfloat16 hz = __float2bfloat16_rn(v.z);
    __nv_bfloat16 hw = __float2bfloat16_rn(v.w);
    __nv_bfloat16 lx = __float2bfloat16_rn(v.x - __bfloat162float(hx));
    __nv_bfloat16 ly = __float2bfloat16_rn(v.y - __bfloat162float(hy));
    __nv_bfloat16 lz = __float2bfloat16_rn(v.z - __bfloat162float(hz));
    __nv_bfloat16 lw = __float2bfloat16_rn(v.w - __bfloat162float(hw));
    reinterpret_cast<__nv_bfloat162*>(hi_arr)[2 * i]     = __nv_bfloat162(hx, hy);
    reinterpret_cast<__nv_bfloat162*>(hi_arr)[2 * i + 1] = __nv_bfloat162(hz, hw);
    reinterpret_cast<__nv_bfloat162*>(lo_arr)[2 * i]     = __nv_bfloat162(lx, ly);
    reinterpret_cast<__nv_bfloat162*>(lo_arr)[2 * i + 1] = __nv_bfloat162(lz, lw);
}

__global__ __launch_bounds__(256) void prep_kernel(
    const float* __restrict__ fc_w,
    const int* __restrict__ adj_row)
{
    const int b = blockIdx.x;
    const int t = threadIdx.x;
    if (b < WBLK) {
        const int i0 = b * 2048 + t;
        float4 v[8];
#pragma unroll
        for (int k = 0; k < 8; k++)
            v[k] = reinterpret_cast<const float4*>(fc_w)[i0 + k * 256];
#pragma unroll
        for (int k = 0; k < 8; k++)
            split4(v[k], g_whi, g_wlo, i0 + k * 256);
    } else {
        // rowptr[r] = lower_bound(adj_row, r) via scatter:
        // thread e fills rowptr[r] = e for r in (adj_row[e-1], adj_row[e]].
        int e = (b - WBLK) * 256 + t;
        if (e > N_EDGES) return;
        int prev = (e == 0) ? -1 : adj_row[e - 1];
        int cur  = (e == N_EDGES) ? M_NODES : adj_row[e];
        for (int r = prev + 1; r <= cur; r++)
            g_rowptr[r] = e;
    }
}

// ---------------------------------------------------------------------------
// Tensor-core GEMM (mma.sync bf16, 3-term split), in-kernel A split.
// CTA 128x128, BK=32, 256 threads = 8 warps (2m x 4n), warp tile 64x32.
// ---------------------------------------------------------------------------
#define BM 128
#define BN 128
#define BK 32
#define KSTRIDE 40
#define A_HI_E   0
#define A_LO_E   5120
#define B_HI_E   10240
#define B_LO_E   15360
#define STAGE_E  20480
#define SMEM_BYTES (2 * STAGE_E * 2)      // 81920 -> 2 CTAs/SM

__device__ __forceinline__ void cp_async16(uint32_t dst, const void* src)
{
    asm volatile("cp.async.cg.shared.global [%0], [%1], 16;\n"
                 :: "r"(dst), "l"(src));
}
__device__ __forceinline__ void cp_commit() { asm volatile("cp.async.commit_group;\n"); }
__device__ __forceinline__ void cp_wait0()  { asm volatile("cp.async.wait_group 0;\n"); }

#define LDSM_X4(r0, r1, r2, r3, addr) \
    asm volatile("ldmatrix.sync.aligned.m8n8.x4.shared.b16 {%0,%1,%2,%3}, [%4];" \
                 : "=r"(r0), "=r"(r1), "=r"(r2), "=r"(r3) : "r"(addr))

#define STS128(addr, r0, r1, r2, r3) \
    asm volatile("st.shared.v4.b32 [%0], {%1,%2,%3,%4};" \
                 :: "r"(addr), "r"(r0), "r"(r1), "r"(r2), "r"(r3) : "memory")

__device__ __forceinline__ void mma_bf16(float c[4], const uint32_t a[4],
                                         const uint32_t b[2])
{
    asm volatile(
        "mma.sync.aligned.m16n8k16.row.col.f32.bf16.bf16.f32 "
        "{%0,%1,%2,%3}, {%4,%5,%6,%7}, {%8,%9}, {%0,%1,%2,%3};\n"
        : "+f"(c[0]), "+f"(c[1]), "+f"(c[2]), "+f"(c[3])
        : "r"(a[0]), "r"(a[1]), "r"(a[2]), "r"(a[3]), "r"(b[0]), "r"(b[1]));
}

__device__ __forceinline__ uint32_t pack_bf2(__nv_bfloat16 a, __nv_bfloat16 b)
{
    __nv_bfloat162 t(a, b);
    return *reinterpret_cast<uint32_t*>(&t);
}

__global__ __launch_bounds__(256) void gemm_tc_kernel(const float* __restrict__ X)
{
    extern __shared__ __nv_bfloat16 smem[];
    const int tid  = threadIdx.x;
    const int lane = tid & 31;
    const int wid  = tid >> 5;
    const int wm   = (wid & 1) * 64;
    const int wn   = (wid >> 1) * 32;
    const int m0   = blockIdx.y * BM;
    const int n0   = blockIdx.x * BN;
    const int grp  = lane >> 2;
    const int tig  = lane & 3;

    const uint32_t smem_u32 = (uint32_t)__cvta_generic_to_shared(smem);

    float acc[4][4][4];
#pragma unroll
    for (int mi = 0; mi < 4; mi++)
#pragma unroll
        for (int ni = 0; ni < 4; ni++)
#pragma unroll
            for (int q = 0; q < 4; q++) acc[mi][ni][q] = 0.f;

    const int rowA  = tid >> 1;
    const int halfA = tid & 1;
    int gmA = m0 + rowA;
    if (gmA >= M_NODES) gmA = 0;
    const float* Xrow = X + (size_t)gmA * K_IN + halfA * 16;

    auto ldg_A = [&](int k0, float4 v[4]) {
        const float4* p = reinterpret_cast<const float4*>(Xrow + k0);
        v[0] = __ldg(p);
        v[1] = __ldg(p + 1);
        v[2] = __ldg(p + 2);
        v[3] = __ldg(p + 3);
    };

    auto sts_A = [&](int buf, const float4 v[4]) {
        uint32_t hi[8], lo[8];
#pragma unroll
        for (int j = 0; j < 4; j++) {
            __nv_bfloat16 hx = __float2bfloat16_rn(v[j].x);
            __nv_bfloat16 hy = __float2bfloat16_rn(v[j].y);
            __nv_bfloat16 hz = __float2bfloat16_rn(v[j].z);
            __nv_bfloat16 hw = __float2bfloat16_rn(v[j].w);
            hi[2 * j]     = pack_bf2(hx, hy);
            hi[2 * j + 1] = pack_bf2(hz, hw);
            lo[2 * j]     = pack_bf2(__float2bfloat16_rn(v[j].x - __bfloat162float(hx)),
                                     __float2bfloat16_rn(v[j].y - __bfloat162float(hy)));
            lo[2 * j + 1] = pack_bf2(__float2bfloat16_rn(v[j].z - __bfloat162float(hz)),
                                     __float2bfloat16_rn(v[j].w - __bfloat162float(hw)));
        }
        uint32_t base = smem_u32 +
            (uint32_t)(buf * STAGE_E + rowA * KSTRIDE + halfA * 16) * 2;
        STS128(base,      hi[0], hi[1], hi[2], hi[3]);
        STS128(base + 16, hi[4], hi[5], hi[6], hi[7]);
        uint32_t basel = base + A_LO_E * 2;
        STS128(basel,      lo[0], lo[1], lo[2], lo[3]);
        STS128(basel + 16, lo[4], lo[5], lo[6], lo[7]);
    };

    auto load_B = [&](int buf, int k0) {
        uint32_t sbase = smem_u32 + (uint32_t)(buf * STAGE_E) * 2;
#pragma unroll
        for (int rep = 0; rep < 2; rep++) {
            int task = tid + rep * 256;
            int row  = task >> 2;
            int ch   = task & 3;
            int gn   = n0 + row;
            uint32_t dB = sbase + (uint32_t)(B_HI_E + row * KSTRIDE + ch * 8) * 2;
            cp_async16(dB,                         &g_whi[(size_t)gn * K_IN + k0 + ch * 8]);
            cp_async16(dB + (B_LO_E - B_HI_E) * 2, &g_wlo[(size_t)gn * K_IN + k0 + ch * 8]);
        }
        cp_commit();
    };

    float4 av[4];
    ldg_A(0, av);
    load_B(0, 0);
    sts_A(0, av);
    ldg_A(BK, av);

    const int a_row = wm + ((lane >> 3) & 1) * 8 + (lane & 7);
    const int a_seg = (lane >> 4) * 8;
    const int b_row = wn + (lane >> 4) * 8 + (lane & 7);
    const int b_seg = ((lane >> 3) & 1) * 8;

    const int NT = K_IN / BK;
    for (int t = 0; t < NT; t++) {
        cp_wait0();
        __syncthreads();

        if (t + 1 < NT) {
            sts_A((t + 1) & 1, av);
            load_B((t + 1) & 1, (t + 1) * BK);
            if (t + 2 < NT) ldg_A((t + 2) * BK, av);
        }

        const uint32_t sbase = smem_u32 + (uint32_t)((t & 1) * STAGE_E) * 2;

#pragma unroll
        for (int ks = 0; ks < 2; ks++) {
            const int kcol = ks * 16;

            uint32_t ahi[4][4];
#pragma unroll
            for (int mi = 0; mi < 4; mi++) {
                uint32_t addr = sbase + (uint32_t)((a_row + mi * 16) * KSTRIDE + a_seg + kcol) * 2;
                LDSM_X4(ahi[mi][0], ahi[mi][1], ahi[mi][2], ahi[mi][3], addr);
            }
            uint32_t bhi[4][2], blo[4][2];
#pragma unroll
            for (int njp = 0; njp < 2; njp++) {
                uint32_t addr = sbase + (uint32_t)(B_HI_E + (b_row + njp * 16) * KSTRIDE + b_seg + kcol) * 2;
                LDSM_X4(bhi[njp * 2][0], bhi[njp * 2][1],
                        bhi[njp * 2 + 1][0], bhi[njp * 2 + 1][1], addr);
                LDSM_X4(blo[njp * 2][0], blo[njp * 2][1],
                        blo[njp * 2 + 1][0], blo[njp * 2 + 1][1], addr + (B_LO_E - B_HI_E) * 2);
            }

#pragma unroll
            for (int mi = 0; mi < 4; mi++)
#pragma unroll
                for (int nj = 0; nj < 4; nj++)
                    mma_bf16(acc[mi][nj], ahi[mi], bhi[nj]);
#pragma unroll
            for (int mi = 0; mi < 4; mi++)
#pragma unroll
                for (int nj = 0; nj < 4; nj++)
                    mma_bf16(acc[mi][nj], ahi[mi], blo[nj]);
            uint32_t alo[4][4];
#pragma unroll
            for (int mi = 0; mi < 4; mi++) {
                uint32_t addr = sbase + (uint32_t)(A_LO_E + (a_row + mi * 16) * KSTRIDE + a_seg + kcol) * 2;
                LDSM_X4(alo[mi][0], alo[mi][1], alo[mi][2], alo[mi][3], addr);
            }
#pragma unroll
            for (int mi = 0; mi < 4; mi++)
#pragma unroll
                for (int nj = 0; nj < 4; nj++)
                    mma_bf16(acc[mi][nj], alo[mi], bhi[nj]);
        }
    }

    // --- epilogue: fp32 acc -> fp16 x_fts ---
#pragma unroll
    for (int mi = 0; mi < 4; mi++) {
        int gm = m0 + wm + mi * 16 + grp;
#pragma unroll
        for (int nj = 0; nj < 4; nj++) {
            int gn = n0 + wn + nj * 8 + tig * 2;
            if (gm < M_NODES) {
                __half2 h = __float22half2_rn(make_float2(acc[mi][nj][0], acc[mi][nj][1]));
                *reinterpret_cast<__half2*>(&g_xfts_h[(size_t)gm * N_HID + gn]) = h;
            }
            if (gm + 8 < M_NODES) {
                __half2 h = __float22half2_rn(make_float2(acc[mi][nj][2], acc[mi][nj][3]));
                *reinterpret_cast<__half2*>(&g_xfts_h[(size_t)(gm + 8) * N_HID + gn]) = h;
            }
        }
    }
}

// ---------------------------------------------------------------------------
// SPMM + bias + PReLU: 2 rows/CTA, 64 threads/row, one LDG.128 per edge-thread
// (8 halves = 16B), fp32 accumulate, 4-deep MLP.
// ---------------------------------------------------------------------------
__global__ __launch_bounds__(128) void spmm_bias_prelu_kernel(
    const float* __restrict__ adj_vals,
    const int* __restrict__ adj_col,
    const float* __restrict__ bias,
    const float* __restrict__ prelu_a,
    float* __restrict__ out)
{
    const int sub = threadIdx.x >> 6;            // 0/1: which row
    const int lt  = threadIdx.x & 63;            // lane within row
    const int r   = blockIdx.x * 2 + sub;        // M_NODES even -> always valid
    const int c   = lt * 8;                      // half index (8 halves/thread)
    const int start = g_rowptr[r];
    const int end   = g_rowptr[r + 1];

    float acc[4][8];
#pragma unroll
    for (int q = 0; q < 4; q++)
#pragma unroll
        for (int j = 0; j < 8; j++) acc[q][j] = 0.f;

    auto gather = [&](int e, float f[8]) {
        const int col = __ldg(&adj_col[e]);
        uint4 u = __ldg(reinterpret_cast<const uint4*>(
            &g_xfts_h[(size_t)col * N_HID + c]));
        float2 p0 = __half22float2(*reinterpret_cast<__half2*>(&u.x));
        float2 p1 = __half22float2(*reinterpret_cast<__half2*>(&u.y));
        float2 p2 = __half22float2(*reinterpret_cast<__half2*>(&u.z));
        float2 p3 = __half22float2(*reinterpret_cast<__half2*>(&u.w));
        f[0] = p0.x; f[1] = p0.y; f[2] = p1.x; f[3] = p1.y;
        f[4] = p2.x; f[5] = p2.y; f[6] = p3.x; f[7] = p3.y;
    };

    int e = start;
    for (; e + 3 < end; e += 4) {
        float v[4];
#pragma unroll
        for (int q = 0; q < 4; q++) v[q] = __ldg(&adj_vals[e + q]);
        float f[4][8];
#pragma unroll
        for (int q = 0; q < 4; q++) gather(e + q, f[q]);
#pragma unroll
        for (int q = 0; q < 4; q++)
#pragma unroll
            for (int j = 0; j < 8; j++)
                acc[q][j] += v[q] * f[q][j];
    }
    for (; e < end; e++) {
        float v0 = __ldg(&adj_vals[e]);
        float f[8];
        gather(e, f);
#pragma unroll
        for (int j = 0; j < 8; j++) acc[0][j] += v0 * f[j];
    }

    const float4 b0 = *reinterpret_cast<const float4*>(&bias[c]);
    const float4 b1 = *reinterpret_cast<const float4*>(&bias[c + 4]);
    const float a = *prelu_a;
    float o[8];
#pragma unroll
    for (int j = 0; j < 8; j++)
        o[j] = (acc[0][j] + acc[1][j]) + (acc[2][j] + acc[3][j]);
    o[0] += b0.x; o[1] += b0.y; o[2] += b0.z; o[3] += b0.w;
    o[4] += b1.x; o[5] += b1.y; o[6] += b1.z; o[7] += b1.w;
#pragma unroll
    for (int j = 0; j < 8; j++)
        o[j] = (o[j] >= 0.f) ? o[j] : a * o[j];

    float* dst = &out[(size_t)r * N_HID + c];
    *reinterpret_cast<float4*>(dst)     = make_float4(o[0], o[1], o[2], o[3]);
    *reinterpret_cast<float4*>(dst + 4) = make_float4(o[4], o[5], o[6], o[7]);
}

extern "C" void kernel_launch(void* const* d_in, const int* in_sizes, int n_in,
                              void* d_out, int out_size)
{
    const float* x        = (const float*)d_in[0];
    const float* fc_w     = (const float*)d_in[1];
    const float* bias     = (const float*)d_in[2];
    const float* prelu_a  = (const float*)d_in[3];
    const float* adj_vals = (const float*)d_in[4];
    const int*   adj_row  = (const int*)d_in[5];
    const int*   adj_col  = (const int*)d_in[6];
    float*       out      = (float*)d_out;

    cudaFuncSetAttribute(gemm_tc_kernel,
                         cudaFuncAttributeMaxDynamicSharedMemorySize, SMEM_BYTES);

    prep_kernel<<<WBLK + RPBLK, 256>>>(fc_w, adj_row);

    dim3 ggrid(N_HID / BN, (M_NODES + BM - 1) / BM);   // 4 x 79
    gemm_tc_kernel<<<ggrid, 256, SMEM_BYTES>>>(x);

    spmm_bias_prelu_kernel<<<M_NODES / 2, 128>>>(adj_vals, adj_col, bias, prelu_a, out);
}

// round 13
// speedup vs baseline: 1.7918x; 1.5111x over previous
#include <cuda_runtime.h>
#include <cuda_fp16.h>
#include <cstdint>

#define M_NODES 10000
#define K_IN    512
#define N_HID   512
#define N_EDGES 160000

// Scratch (no allocations allowed)
__device__ __half g_xfts_h[M_NODES * N_HID];   // fp16 x_fts (L2-resident, 10 MB)
__device__ __half g_wh[N_HID * K_IN];          // fp16 weights
__device__ int    g_rowptr[M_NODES + 1];

// ---------------------------------------------------------------------------
// Prep: convert W fp32 -> fp16, rowptr via edge-parallel scatter.
// ---------------------------------------------------------------------------
#define WBLK 32
#define RPBLK 626

__global__ __launch_bounds__(256) void prep_kernel(
    const float* __restrict__ fc_w,
    const int* __restrict__ adj_row)
{
    const int b = blockIdx.x;
    const int t = threadIdx.x;
    if (b < WBLK) {
        const int i0 = b * 2048 + t;
        float4 v[8];
#pragma unroll
        for (int k = 0; k < 8; k++)
            v[k] = reinterpret_cast<const float4*>(fc_w)[i0 + k * 256];
#pragma unroll
        for (int k = 0; k < 8; k++) {
            int i = i0 + k * 256;
            __half2 h0 = __floats2half2_rn(v[k].x, v[k].y);
            __half2 h1 = __floats2half2_rn(v[k].z, v[k].w);
            reinterpret_cast<__half2*>(g_wh)[2 * i]     = h0;
            reinterpret_cast<__half2*>(g_wh)[2 * i + 1] = h1;
        }
    } else {
        // rowptr[r] = lower_bound(adj_row, r) via scatter
        int e = (b - WBLK) * 256 + t;
        if (e > N_EDGES) return;
        int prev = (e == 0) ? -1 : adj_row[e - 1];
        int cur  = (e == N_EDGES) ? M_NODES : adj_row[e];
        for (int r = prev + 1; r <= cur; r++)
            g_rowptr[r] = e;
    }
}

// ---------------------------------------------------------------------------
// Tensor-core GEMM (mma.sync fp16, single term), in-kernel A conversion.
// CTA 128x128, BK=32, 256 threads = 8 warps (2m x 4n), warp tile 64x32.
// A: fp32 LDG register-prefetch -> fp16 -> STS double buffer.
// B: cp.async double buffer from g_wh.  Epilogue: fp32 acc -> fp16.
// ---------------------------------------------------------------------------
#define BM 128
#define BN 128
#define BK 32
#define KSTRIDE 40
#define A_E      0
#define B_E      5120
#define STAGE_E  10240
#define SMEM_BYTES (2 * STAGE_E * 2)      // 40960

__device__ __forceinline__ void cp_async16(uint32_t dst, const void* src)
{
    asm volatile("cp.async.cg.shared.global [%0], [%1], 16;\n"
                 :: "r"(dst), "l"(src));
}
__device__ __forceinline__ void cp_commit() { asm volatile("cp.async.commit_group;\n"); }
__device__ __forceinline__ void cp_wait0()  { asm volatile("cp.async.wait_group 0;\n"); }

#define LDSM_X4(r0, r1, r2, r3, addr) \
    asm volatile("ldmatrix.sync.aligned.m8n8.x4.shared.b16 {%0,%1,%2,%3}, [%4];" \
                 : "=r"(r0), "=r"(r1), "=r"(r2), "=r"(r3) : "r"(addr))

#define STS128(addr, r0, r1, r2, r3) \
    asm volatile("st.shared.v4.b32 [%0], {%1,%2,%3,%4};" \
                 :: "r"(addr), "r"(r0), "r"(r1), "r"(r2), "r"(r3) : "memory")

__device__ __forceinline__ void mma_f16(float c[4], const uint32_t a[4],
                                        const uint32_t b[2])
{
    asm volatile(
        "mma.sync.aligned.m16n8k16.row.col.f32.f16.f16.f32 "
        "{%0,%1,%2,%3}, {%4,%5,%6,%7}, {%8,%9}, {%0,%1,%2,%3};\n"
        : "+f"(c[0]), "+f"(c[1]), "+f"(c[2]), "+f"(c[3])
        : "r"(a[0]), "r"(a[1]), "r"(a[2]), "r"(a[3]), "r"(b[0]), "r"(b[1]));
}

__device__ __forceinline__ uint32_t pack_h2(float a, float b)
{
    __half2 t = __floats2half2_rn(a, b);
    return *reinterpret_cast<uint32_t*>(&t);
}

__global__ __launch_bounds__(256) void gemm_tc_kernel(const float* __restrict__ X)
{
    extern __shared__ __half smem[];
    const int tid  = threadIdx.x;
    const int lane = tid & 31;
    const int wid  = tid >> 5;
    const int wm   = (wid & 1) * 64;
    const int wn   = (wid >> 1) * 32;
    const int m0   = blockIdx.y * BM;
    const int n0   = blockIdx.x * BN;
    const int grp  = lane >> 2;
    const int tig  = lane & 3;

    const uint32_t smem_u32 = (uint32_t)__cvta_generic_to_shared(smem);

    float acc[4][4][4];
#pragma unroll
    for (int mi = 0; mi < 4; mi++)
#pragma unroll
        for (int ni = 0; ni < 4; ni++)
#pragma unroll
            for (int q = 0; q < 4; q++) acc[mi][ni][q] = 0.f;

    const int rowA  = tid >> 1;
    const int halfA = tid & 1;
    int gmA = m0 + rowA;
    if (gmA >= M_NODES) gmA = 0;
    const float* Xrow = X + (size_t)gmA * K_IN + halfA * 16;

    auto ldg_A = [&](int k0, float4 v[4]) {
        const float4* p = reinterpret_cast<const float4*>(Xrow + k0);
        v[0] = __ldg(p);
        v[1] = __ldg(p + 1);
        v[2] = __ldg(p + 2);
        v[3] = __ldg(p + 3);
    };

    auto sts_A = [&](int buf, const float4 v[4]) {
        uint32_t h[8];
#pragma unroll
        for (int j = 0; j < 4; j++) {
            h[2 * j]     = pack_h2(v[j].x, v[j].y);
            h[2 * j + 1] = pack_h2(v[j].z, v[j].w);
        }
        uint32_t base = smem_u32 +
            (uint32_t)(buf * STAGE_E + rowA * KSTRIDE + halfA * 16) * 2;
        STS128(base,      h[0], h[1], h[2], h[3]);
        STS128(base + 16, h[4], h[5], h[6], h[7]);
    };

    auto load_B = [&](int buf, int k0) {
        uint32_t sbase = smem_u32 + (uint32_t)(buf * STAGE_E) * 2;
#pragma unroll
        for (int rep = 0; rep < 2; rep++) {
            int task = tid + rep * 256;
            int row  = task >> 2;
            int ch   = task & 3;
            int gn   = n0 + row;
            uint32_t dB = sbase + (uint32_t)(B_E + row * KSTRIDE + ch * 8) * 2;
            cp_async16(dB, &g_wh[(size_t)gn * K_IN + k0 + ch * 8]);
        }
        cp_commit();
    };

    float4 av[4];
    ldg_A(0, av);
    load_B(0, 0);
    sts_A(0, av);
    ldg_A(BK, av);

    const int a_row = wm + ((lane >> 3) & 1) * 8 + (lane & 7);
    const int a_seg = (lane >> 4) * 8;
    const int b_row = wn + (lane >> 4) * 8 + (lane & 7);
    const int b_seg = ((lane >> 3) & 1) * 8;

    const int NT = K_IN / BK;
    for (int t = 0; t < NT; t++) {
        cp_wait0();
        __syncthreads();

        if (t + 1 < NT) {
            sts_A((t + 1) & 1, av);
            load_B((t + 1) & 1, (t + 1) * BK);
            if (t + 2 < NT) ldg_A((t + 2) * BK, av);
        }

        const uint32_t sbase = smem_u32 + (uint32_t)((t & 1) * STAGE_E) * 2;

#pragma unroll
        for (int ks = 0; ks < 2; ks++) {
            const int kcol = ks * 16;

            uint32_t a[4][4];
#pragma unroll
            for (int mi = 0; mi < 4; mi++) {
                uint32_t addr = sbase + (uint32_t)((a_row + mi * 16) * KSTRIDE + a_seg + kcol) * 2;
                LDSM_X4(a[mi][0], a[mi][1], a[mi][2], a[mi][3], addr);
            }
            uint32_t b[4][2];
#pragma unroll
            for (int njp = 0; njp < 2; njp++) {
                uint32_t addr = sbase + (uint32_t)(B_E + (b_row + njp * 16) * KSTRIDE + b_seg + kcol) * 2;
                LDSM_X4(b[njp * 2][0], b[njp * 2][1],
                        b[njp * 2 + 1][0], b[njp * 2 + 1][1], addr);
            }
#pragma unroll
            for (int mi = 0; mi < 4; mi++)
#pragma unroll
                for (int nj = 0; nj < 4; nj++)
                    mma_f16(acc[mi][nj], a[mi], b[nj]);
        }
    }

    // --- epilogue: fp32 acc -> fp16 x_fts ---
#pragma unroll
    for (int mi = 0; mi < 4; mi++) {
        int gm = m0 + wm + mi * 16 + grp;
#pragma unroll
        for (int nj = 0; nj < 4; nj++) {
            int gn = n0 + wn + nj * 8 + tig * 2;
            if (gm < M_NODES) {
                __half2 h = __float22half2_rn(make_float2(acc[mi][nj][0], acc[mi][nj][1]));
                *reinterpret_cast<__half2*>(&g_xfts_h[(size_t)gm * N_HID + gn]) = h;
            }
            if (gm + 8 < M_NODES) {
                __half2 h = __float22half2_rn(make_float2(acc[mi][nj][2], acc[mi][nj][3]));
                *reinterpret_cast<__half2*>(&g_xfts_h[(size_t)(gm + 8) * N_HID + gn]) = h;
            }
        }
    }
}

// ---------------------------------------------------------------------------
// SPMM + bias + PReLU: 2 rows/CTA, 64 threads/row, one LDG.128 per edge-thread.
// ---------------------------------------------------------------------------
__global__ __launch_bounds__(128) void spmm_bias_prelu_kernel(
    const float* __restrict__ adj_vals,
    const int* __restrict__ adj_col,
    const float* __restrict__ bias,
    const float* __restrict__ prelu_a,
    float* __restrict__ out)
{
    const int sub = threadIdx.x >> 6;
    const int lt  = threadIdx.x & 63;
    const int r   = blockIdx.x * 2 + sub;
    const int c   = lt * 8;
    const int start = g_rowptr[r];
    const int end   = g_rowptr[r + 1];

    float acc[4][8];
#pragma unroll
    for (int q = 0; q < 4; q++)
#pragma unroll
        for (int j = 0; j < 8; j++) acc[q][j] = 0.f;

    auto gather = [&](int e, float f[8]) {
        const int col = __ldg(&adj_col[e]);
        uint4 u = __ldg(reinterpret_cast<const uint4*>(
            &g_xfts_h[(size_t)col * N_HID + c]));
        float2 p0 = __half22float2(*reinterpret_cast<__half2*>(&u.x));
        float2 p1 = __half22float2(*reinterpret_cast<__half2*>(&u.y));
        float2 p2 = __half22float2(*reinterpret_cast<__half2*>(&u.z));
        float2 p3 = __half22float2(*reinterpret_cast<__half2*>(&u.w));
        f[0] = p0.x; f[1] = p0.y; f[2] = p1.x; f[3] = p1.y;
        f[4] = p2.x; f[5] = p2.y; f[6] = p3.x; f[7] = p3.y;
    };

    int e = start;
    for (; e + 3 < end; e += 4) {
        float v[4];
#pragma unroll
        for (int q = 0; q < 4; q++) v[q] = __ldg(&adj_vals[e + q]);
        float f[4][8];
#pragma unroll
        for (int q = 0; q < 4; q++) gather(e + q, f[q]);
#pragma unroll
        for (int q = 0; q < 4; q++)
#pragma unroll
            for (int j = 0; j < 8; j++)
                acc[q][j] += v[q] * f[q][j];
    }
    for (; e < end; e++) {
        float v0 = __ldg(&adj_vals[e]);
        float f[8];
        gather(e, f);
#pragma unroll
        for (int j = 0; j < 8; j++) acc[0][j] += v0 * f[j];
    }

    const float4 b0 = *reinterpret_cast<const float4*>(&bias[c]);
    const float4 b1 = *reinterpret_cast<const float4*>(&bias[c + 4]);
    const float a = *prelu_a;
    float o[8];
#pragma unroll
    for (int j = 0; j < 8; j++)
        o[j] = (acc[0][j] + acc[1][j]) + (acc[2][j] + acc[3][j]);
    o[0] += b0.x; o[1] += b0.y; o[2] += b0.z; o[3] += b0.w;
    o[4] += b1.x; o[5] += b1.y; o[6] += b1.z; o[7] += b1.w;
#pragma unroll
    for (int j = 0; j < 8; j++)
        o[j] = (o[j] >= 0.f) ? o[j] : a * o[j];

    float* dst = &out[(size_t)r * N_HID + c];
    *reinterpret_cast<float4*>(dst)     = make_float4(o[0], o[1], o[2], o[3]);
    *reinterpret_cast<float4*>(dst + 4) = make_float4(o[4], o[5], o[6], o[7]);
}

extern "C" void kernel_launch(void* const* d_in, const int* in_sizes, int n_in,
                              void* d_out, int out_size)
{
    const float* x        = (const float*)d_in[0];
    const float* fc_w     = (const float*)d_in[1];
    const float* bias     = (const float*)d_in[2];
    const float* prelu_a  = (const float*)d_in[3];
    const float* adj_vals = (const float*)d_in[4];
    const int*   adj_row  = (const int*)d_in[5];
    const int*   adj_col  = (const int*)d_in[6];
    float*       out      = (float*)d_out;

    cudaFuncSetAttribute(gemm_tc_kernel,
                         cudaFuncAttributeMaxDynamicSharedMemorySize, SMEM_BYTES);

    prep_kernel<<<WBLK + RPBLK, 256>>>(fc_w, adj_row);

    dim3 ggrid(N_HID / BN, (M_NODES + BM - 1) / BM);   // 4 x 79
    gemm_tc_kernel<<<ggrid, 256, SMEM_BYTES>>>(x);

    spmm_bias_prelu_kernel<<<M_NODES / 2, 128>>>(adj_vals, adj_col, bias, prelu_a, out);
}